// round 2
// baseline (speedup 1.0000x reference)
#include <cuda_runtime.h>
#include <math.h>

// Problem constants (fixed by the dataset):
//   b=4, n=4096 -> T = 16384 tokens, dim=1024, heads=16, d=64
#define TOKENS 16384
#define DIM    1024
#define QKVDIM 3072
#define NHEAD  16
#define HDIM   64
#define SEQ    4096

// Scratch: qkv (T x 3*dim) and attention output (T x dim), fp32.
__device__ float g_qkv[(size_t)TOKENS * QKVDIM];
__device__ float g_att[(size_t)TOKENS * DIM];

// ---------------------------------------------------------------------------
// Classic fp32 SGEMM: C[M,N] = A[M,K] @ B[K,N] (+ bias), row-major.
// BM=BN=128, BK=8, 256 threads, 8x8 register tile per thread.
// M,N,K here are always multiples of the tile sizes -> no bounds checks.
// ---------------------------------------------------------------------------
#define BM 128
#define BN 128
#define BKK 8
#define TM 8
#define TN 8

template <bool BIAS>
__global__ __launch_bounds__(256, 2)
void sgemm_kernel(const float* __restrict__ A, const float* __restrict__ B,
                  const float* __restrict__ bias, float* __restrict__ C,
                  int M, int N, int K) {
    __shared__ float As[BKK][BM];   // transposed A tile
    __shared__ float Bs[BKK][BN];

    const int tid = threadIdx.x;
    const long bx = blockIdx.x;     // N-tile
    const long by = blockIdx.y;     // M-tile

    const float* Ab = A + by * BM * (long)K;
    const float* Bb = B + bx * BN;

    float acc[TM][TN];
#pragma unroll
    for (int i = 0; i < TM; i++)
#pragma unroll
        for (int j = 0; j < TN; j++) acc[i][j] = 0.f;

    const int arow = tid >> 1;            // 0..127
    const int acol = (tid & 1) * 4;       // 0 or 4
    const int brow = tid >> 5;            // 0..7
    const int bcol = (tid & 31) * 4;      // 0..124
    const int ty = tid >> 4;              // 0..15
    const int tx = tid & 15;              // 0..15

    for (int k0 = 0; k0 < K; k0 += BKK) {
        float4 a = *(const float4*)(Ab + (long)arow * K + k0 + acol);
        As[acol + 0][arow] = a.x;
        As[acol + 1][arow] = a.y;
        As[acol + 2][arow] = a.z;
        As[acol + 3][arow] = a.w;
        *(float4*)&Bs[brow][bcol] =
            *(const float4*)(Bb + (long)(k0 + brow) * N + bcol);
        __syncthreads();

#pragma unroll
        for (int k = 0; k < BKK; k++) {
            float ra[TM], rb[TN];
            *(float4*)&ra[0] = *(const float4*)&As[k][ty * TM];
            *(float4*)&ra[4] = *(const float4*)&As[k][ty * TM + 4];
            *(float4*)&rb[0] = *(const float4*)&Bs[k][tx * TN];
            *(float4*)&rb[4] = *(const float4*)&Bs[k][tx * TN + 4];
#pragma unroll
            for (int i = 0; i < TM; i++)
#pragma unroll
                for (int j = 0; j < TN; j++)
                    acc[i][j] = fmaf(ra[i], rb[j], acc[i][j]);
        }
        __syncthreads();
    }

#pragma unroll
    for (int i = 0; i < TM; i++) {
        long row = by * BM + ty * TM + i;
        float* Crow = C + row * (long)N + bx * BN;
#pragma unroll
        for (int j4 = 0; j4 < TN; j4 += 4) {
            int col = tx * TN + j4;
            float4 v;
            v.x = acc[i][j4 + 0];
            v.y = acc[i][j4 + 1];
            v.z = acc[i][j4 + 2];
            v.w = acc[i][j4 + 3];
            if (BIAS) {
                long gc = bx * BN + col;
                v.x += bias[gc + 0];
                v.y += bias[gc + 1];
                v.z += bias[gc + 2];
                v.w += bias[gc + 3];
            }
            *(float4*)(Crow + col) = v;
        }
    }
}

// ---------------------------------------------------------------------------
// Fused per-token middle stage: RMSNorm(q,k) -> RoPE(q,k) -> scores (16x16)
// -> softmax -> out = attn @ v. One block (128 threads) per token.
// ---------------------------------------------------------------------------
__global__ __launch_bounds__(128)
void attn_kernel(const float* __restrict__ qkv,
                 const float* __restrict__ fcos, const float* __restrict__ fsin,
                 const float* __restrict__ g_q, const float* __restrict__ g_k,
                 float* __restrict__ out) {
    const int token = blockIdx.x;
    const int n_idx = token & (SEQ - 1);
    const float* row = qkv + (size_t)token * QKVDIM;

    __shared__ float sq[NHEAD][HDIM];
    __shared__ float sk[NHEAD][HDIM];
    __shared__ float sv[NHEAD][HDIM];
    __shared__ float sc[HDIM / 2], ss[HDIM / 2];
    __shared__ float sscore[NHEAD][NHEAD + 1];

    const int tid = threadIdx.x;

    // Load q, k, v for this token into smem (coalesced float4 loads).
    for (int i = tid; i < DIM / 4; i += 128) {
        ((float4*)&sq[0][0])[i] = ((const float4*)row)[i];
        ((float4*)&sk[0][0])[i] = ((const float4*)(row + DIM))[i];
        ((float4*)&sv[0][0])[i] = ((const float4*)(row + 2 * DIM))[i];
    }
    if (tid < HDIM / 2) {
        sc[tid] = fcos[(size_t)n_idx * (HDIM / 2) + tid];
        ss[tid] = fsin[(size_t)n_idx * (HDIM / 2) + tid];
    }
    __syncthreads();

    // RMSNorm + RoPE: 32 tasks (16 q-heads, 16 k-heads), 4 threads each.
    {
        const int task = tid >> 2;   // 0..31
        const int l4 = tid & 3;      // 0..3
        const int hh = task & (NHEAD - 1);
        float* vec = (task < NHEAD) ? sq[hh] : sk[hh];
        const float* g = (task < NHEAD) ? g_q : g_k;

        float ssum = 0.f;
        const int e0 = l4 * 16;
#pragma unroll
        for (int e = 0; e < 16; e++) {
            float v = vec[e0 + e];
            ssum += v * v;
        }
        ssum += __shfl_xor_sync(0xffffffffu, ssum, 1);
        ssum += __shfl_xor_sync(0xffffffffu, ssum, 2);
        // nrm = ||x|| * d^-0.5 ; d = 64 -> d^-0.5 = 0.125
        float nrm = sqrtf(ssum) * 0.125f;
        float inv = 1.f / (nrm + 1e-6f);

        const int p0 = l4 * 8;       // 8 complex pairs per thread
#pragma unroll
        for (int p = 0; p < 8; p++) {
            int pp = p0 + p;
            float re = vec[2 * pp] * inv * g[2 * pp];
            float im = vec[2 * pp + 1] * inv * g[2 * pp + 1];
            float c = sc[pp], s = ss[pp];
            vec[2 * pp]     = re * c - im * s;
            vec[2 * pp + 1] = re * s + im * c;
        }
    }
    __syncthreads();

    // Scores: 16x16 = 256 dot products over d=64; 2 per thread.
    for (int e = tid; e < NHEAD * NHEAD; e += 128) {
        int i = e >> 4, j = e & 15;
        float acc = 0.f;
#pragma unroll
        for (int dd = 0; dd < HDIM; dd++) acc += sq[i][dd] * sk[j][dd];
        sscore[i][j] = acc * 0.125f;   // scale = d^-0.5
    }
    __syncthreads();

    // Softmax over each 16-wide row (16 threads, one row each).
    if (tid < NHEAD) {
        float mx = -1e30f;
#pragma unroll
        for (int j = 0; j < NHEAD; j++) mx = fmaxf(mx, sscore[tid][j]);
        float sum = 0.f;
#pragma unroll
        for (int j = 0; j < NHEAD; j++) {
            float e2 = expf(sscore[tid][j] - mx);
            sscore[tid][j] = e2;
            sum += e2;
        }
        float r = 1.f / sum;
#pragma unroll
        for (int j = 0; j < NHEAD; j++) sscore[tid][j] *= r;
    }
    __syncthreads();

    // out = attn @ v : 1024 outputs, 8 per thread.
    float* orow = out + (size_t)token * DIM;
    for (int e = tid; e < DIM; e += 128) {
        int i = e >> 6, dd = e & 63;
        float acc = 0.f;
#pragma unroll
        for (int j = 0; j < NHEAD; j++) acc = fmaf(sscore[i][j], sv[j][dd], acc);
        orow[e] = acc;
    }
}

// ---------------------------------------------------------------------------
// Launch: GEMM(qkv) -> fused attention -> GEMM(proj)+bias
// ---------------------------------------------------------------------------
extern "C" void kernel_launch(void* const* d_in, const int* in_sizes, int n_in,
                              void* d_out, int out_size) {
    const float* x     = (const float*)d_in[0];   // (4,4096,1024)
    const float* fcos  = (const float*)d_in[1];   // (1,4096,1,32)
    const float* fsin  = (const float*)d_in[2];   // (1,4096,1,32)
    const float* wqkv  = (const float*)d_in[3];   // (1024,3072)
    const float* gq    = (const float*)d_in[4];   // (64,)
    const float* gk    = (const float*)d_in[5];   // (64,)
    const float* wproj = (const float*)d_in[6];   // (1024,1024)
    const float* bproj = (const float*)d_in[7];   // (1024,)
    float* out = (float*)d_out;                   // (4,4096,1024) fp32

    void* qkv_ptr = nullptr;
    void* att_ptr = nullptr;
    cudaGetSymbolAddress(&qkv_ptr, g_qkv);
    cudaGetSymbolAddress(&att_ptr, g_att);
    float* qkv = (float*)qkv_ptr;
    float* att = (float*)att_ptr;

    // GEMM1: qkv = x @ w_qkv : (16384,1024) @ (1024,3072)
    {
        dim3 grid(QKVDIM / BN, TOKENS / BM);
        sgemm_kernel<false><<<grid, 256>>>(x, wqkv, nullptr, qkv,
                                           TOKENS, QKVDIM, DIM);
    }

    // Fused RMSNorm + RoPE + head-mixing attention (one block per token).
    attn_kernel<<<TOKENS, 128>>>(qkv, fcos, fsin, gq, gk, att);

    // GEMM2: out = att @ w_proj + b_proj : (16384,1024) @ (1024,1024)
    {
        dim3 grid(DIM / BN, TOKENS / BM);
        sgemm_kernel<true><<<grid, 256>>>(att, wproj, bproj, out,
                                          TOKENS, DIM, DIM);
    }
}

// round 4
// speedup vs baseline: 2.5313x; 2.5313x over previous
#include <cuda_runtime.h>
#include <cuda_bf16.h>
#include <stdint.h>
#include <math.h>

// Problem constants: b=4, n=4096 -> T=16384 tokens, dim=1024, heads=16, d=64
#define TOKENS 16384
#define DIM    1024
#define QKVDIM 3072
#define NHEAD  16
#define HDIM   64
#define SEQ    4096

// GEMM tiling (K is always 1024)
#define BM 128
#define BN 128
#define BK 32
#define KCHUNKS (DIM / BK)          // 32
#define STAGES 3
#define ARR_BYTES (BM * BK * 2)     // 8192 per operand array per stage
#define STAGE_BYTES (4 * ARR_BYTES) // 32768 (Ahi, Alo, Bhi, Blo)
#define GEMM_SMEM (STAGES * STAGE_BYTES)  // 98304

// ---------------------------------------------------------------------------
// Scratch (device globals; kernel_launch is allocation-free)
// ---------------------------------------------------------------------------
__device__ __align__(256) __nv_bfloat16 g_xhi [(size_t)TOKENS * DIM];
__device__ __align__(256) __nv_bfloat16 g_xlo [(size_t)TOKENS * DIM];
__device__ __align__(256) __nv_bfloat16 g_wqhi[(size_t)QKVDIM * DIM]; // [N,K]
__device__ __align__(256) __nv_bfloat16 g_wqlo[(size_t)QKVDIM * DIM];
__device__ __align__(256) __nv_bfloat16 g_wphi[(size_t)DIM * DIM];    // [N,K]
__device__ __align__(256) __nv_bfloat16 g_wplo[(size_t)DIM * DIM];
__device__ __align__(256) __nv_bfloat16 g_ahi [(size_t)TOKENS * DIM];
__device__ __align__(256) __nv_bfloat16 g_alo [(size_t)TOKENS * DIM];
__device__ __align__(256) float         g_qkv [(size_t)TOKENS * QKVDIM];

// ---------------------------------------------------------------------------
// PTX helpers (baseline sm_80+ features only — no tcgen05 on this target)
// ---------------------------------------------------------------------------
__device__ __forceinline__ uint32_t s2u(const void* p) {
    uint32_t a;
    asm("{ .reg .u64 t; cvta.to.shared.u64 t, %1; cvt.u32.u64 %0, t; }"
        : "=r"(a) : "l"(p));
    return a;
}

__device__ __forceinline__ void cp_async16(uint32_t dst, const void* gsrc) {
    asm volatile("cp.async.cg.shared.global [%0], [%1], 16;"
                 :: "r"(dst), "l"(__cvta_generic_to_global(gsrc)) : "memory");
}
__device__ __forceinline__ void cp_commit() {
    asm volatile("cp.async.commit_group;" ::: "memory");
}
__device__ __forceinline__ void cp_wait1() {
    asm volatile("cp.async.wait_group 1;" ::: "memory");
}

__device__ __forceinline__ void ldsm_x4(uint32_t& r0, uint32_t& r1,
                                        uint32_t& r2, uint32_t& r3, uint32_t addr) {
    asm volatile("ldmatrix.sync.aligned.m8n8.x4.shared.b16 {%0,%1,%2,%3}, [%4];"
                 : "=r"(r0), "=r"(r1), "=r"(r2), "=r"(r3) : "r"(addr));
}
__device__ __forceinline__ void ldsm_x2(uint32_t& r0, uint32_t& r1, uint32_t addr) {
    asm volatile("ldmatrix.sync.aligned.m8n8.x2.shared.b16 {%0,%1}, [%2];"
                 : "=r"(r0), "=r"(r1) : "r"(addr));
}

__device__ __forceinline__ void mma16816(float* c, const uint32_t* a, const uint32_t* b) {
    asm volatile(
        "mma.sync.aligned.m16n8k16.row.col.f32.bf16.bf16.f32 "
        "{%0,%1,%2,%3}, {%4,%5,%6,%7}, {%8,%9}, {%0,%1,%2,%3};"
        : "+f"(c[0]), "+f"(c[1]), "+f"(c[2]), "+f"(c[3])
        : "r"(a[0]), "r"(a[1]), "r"(a[2]), "r"(a[3]), "r"(b[0]), "r"(b[1]));
}

__device__ __forceinline__ void split_bf16(float x, __nv_bfloat16& h, __nv_bfloat16& l) {
    h = __float2bfloat16_rn(x);
    l = __float2bfloat16_rn(x - __bfloat162float(h));
}

// Swizzled smem byte offset for a (row, 16B-unit) within a [128][BK] bf16 tile.
// Row = 64 bytes = 4 units; phys unit = u ^ ((row>>1)&3)  -> conflict-free
// for both cp.async writes and ldmatrix 8-lane phases.
__device__ __forceinline__ uint32_t sw_off(int row, int u) {
    return (uint32_t)(row * 64 + (((u ^ ((row >> 1) & 3)) & 3) << 4));
}

// ---------------------------------------------------------------------------
// GEMM: C[M,N] = A @ B^T, A=[M,1024] bf16 hi/lo, B=[N,1024] bf16 hi/lo.
// 3-term split: hi*hi + hi*lo + lo*hi, fp32 accumulators.
// grid (N/128, M/128), 256 threads (8 warps, each 64x32).
// ---------------------------------------------------------------------------
template <bool BIAS>
__global__ __launch_bounds__(256, 1)
void mma_gemm(const __nv_bfloat16* __restrict__ Ahi, const __nv_bfloat16* __restrict__ Alo,
              const __nv_bfloat16* __restrict__ Bhi, const __nv_bfloat16* __restrict__ Blo,
              const float* __restrict__ bias, float* __restrict__ C, int N) {
    extern __shared__ __align__(256) char smem[];
    const uint32_t sb = s2u(smem);
    const int tid = threadIdx.x;
    const int wid = tid >> 5, lane = tid & 31;
    const int m0 = blockIdx.y * BM;
    const int n0 = blockIdx.x * BN;

    const __nv_bfloat16* bases[4] = {
        Ahi + (size_t)m0 * DIM, Alo + (size_t)m0 * DIM,
        Bhi + (size_t)n0 * DIM, Blo + (size_t)n0 * DIM
    };

    // --- async stage loader: 2048 x 16B units per stage, 8 per thread ---
    auto load_stage = [&](int s, int c) {
#pragma unroll
        for (int i = 0; i < 8; i++) {
            int u = tid + i * 256;
            int arr = u >> 9;            // 0..3
            int idx = u & 511;
            int row = idx >> 2;          // 0..127
            int cu  = idx & 3;           // 16B unit within 64B row
            const char* src = (const char*)bases[arr]
                              + (size_t)row * (DIM * 2) + c * (BK * 2) + cu * 16;
            uint32_t dst = sb + s * STAGE_BYTES + arr * ARR_BYTES + sw_off(row, cu);
            cp_async16(dst, src);
        }
    };

    // prologue
#pragma unroll
    for (int s = 0; s < STAGES - 1; s++) { load_stage(s, s); cp_commit(); }

    const int wr = wid >> 2, wc = wid & 3;   // 2x4 warp grid
    const int wo = wr * 64, no = wc * 32;

    float acc[4][4][4];
#pragma unroll
    for (int mi = 0; mi < 4; mi++)
#pragma unroll
        for (int ni = 0; ni < 4; ni++)
#pragma unroll
            for (int e = 0; e < 4; e++) acc[mi][ni][e] = 0.f;

    const int la = lane & 15;

    for (int c = 0; c < KCHUNKS; c++) {
        cp_wait1();
        __syncthreads();

        const int cn = c + STAGES - 1;
        if (cn < KCHUNKS) load_stage(cn % STAGES, cn);
        cp_commit();

        const uint32_t st = sb + (c % STAGES) * STAGE_BYTES;
        const uint32_t sAh = st;
        const uint32_t sAl = st + ARR_BYTES;
        const uint32_t sBh = st + 2 * ARR_BYTES;
        const uint32_t sBl = st + 3 * ARR_BYTES;

#pragma unroll
        for (int k16 = 0; k16 < 2; k16++) {
            uint32_t ah[4][4], al[4][4], bh[4][2], bl[4][2];
            const int au = k16 * 2 + (lane >> 4);
#pragma unroll
            for (int mi = 0; mi < 4; mi++) {
                const int row = wo + mi * 16 + la;
                uint32_t off = sw_off(row, au);
                ldsm_x4(ah[mi][0], ah[mi][1], ah[mi][2], ah[mi][3], sAh + off);
                ldsm_x4(al[mi][0], al[mi][1], al[mi][2], al[mi][3], sAl + off);
            }
            const int bu = k16 * 2 + ((la >> 3) & 1);
#pragma unroll
            for (int ni = 0; ni < 4; ni++) {
                const int row = no + ni * 8 + (la & 7);
                uint32_t off = sw_off(row, bu);
                ldsm_x2(bh[ni][0], bh[ni][1], sBh + off);
                ldsm_x2(bl[ni][0], bl[ni][1], sBl + off);
            }
            // hi*hi
#pragma unroll
            for (int mi = 0; mi < 4; mi++)
#pragma unroll
                for (int ni = 0; ni < 4; ni++)
                    mma16816(acc[mi][ni], ah[mi], bh[ni]);
            // hi*lo
#pragma unroll
            for (int mi = 0; mi < 4; mi++)
#pragma unroll
                for (int ni = 0; ni < 4; ni++)
                    mma16816(acc[mi][ni], ah[mi], bl[ni]);
            // lo*hi
#pragma unroll
            for (int mi = 0; mi < 4; mi++)
#pragma unroll
                for (int ni = 0; ni < 4; ni++)
                    mma16816(acc[mi][ni], al[mi], bh[ni]);
        }
    }

    // epilogue
    const int tg = lane >> 2, tq = lane & 3;
#pragma unroll
    for (int mi = 0; mi < 4; mi++) {
#pragma unroll
        for (int ni = 0; ni < 4; ni++) {
            const float* cc = acc[mi][ni];
            int col = n0 + no + ni * 8 + tq * 2;
            float bx = 0.f, by = 0.f;
            if (BIAS) { bx = bias[col]; by = bias[col + 1]; }
            size_t r0 = (size_t)(m0 + wo + mi * 16 + tg);
            float2 v0 = {cc[0] + bx, cc[1] + by};
            float2 v1 = {cc[2] + bx, cc[3] + by};
            *(float2*)(C + r0 * N + col) = v0;
            *(float2*)(C + (r0 + 8) * N + col) = v1;
        }
    }
}

// ---------------------------------------------------------------------------
// Conversions
// ---------------------------------------------------------------------------
// x fp32 [M,1024] -> hi/lo bf16 row-major. One thread = 8 elements.
__global__ void convert_A_kernel(const float* __restrict__ X,
                                 __nv_bfloat16* __restrict__ Hi,
                                 __nv_bfloat16* __restrict__ Lo, size_t total8) {
    size_t t = (size_t)blockIdx.x * blockDim.x + threadIdx.x;
    if (t >= total8) return;
    const float* src = X + t * 8;
    float4 f0 = *(const float4*)src;
    float4 f1 = *(const float4*)(src + 4);
    float v[8] = {f0.x, f0.y, f0.z, f0.w, f1.x, f1.y, f1.z, f1.w};
    union { __nv_bfloat16 b[8]; uint4 q; } H, L;
#pragma unroll
    for (int i = 0; i < 8; i++) split_bf16(v[i], H.b[i], L.b[i]);
    ((uint4*)Hi)[t] = H.q;
    ((uint4*)Lo)[t] = L.q;
}

// W fp32 [1024, Nout] -> transposed bf16 hi/lo [Nout, 1024] via smem tile.
__global__ void convert_W_kernel(const float* __restrict__ W,
                                 __nv_bfloat16* __restrict__ Hi,
                                 __nv_bfloat16* __restrict__ Lo, int Nout) {
    __shared__ float tile[32][33];
    const int tx = threadIdx.x & 31, ty = threadIdx.x >> 5;   // 256 threads
    const int n0 = blockIdx.x * 32, k0 = blockIdx.y * 32;
#pragma unroll
    for (int i = 0; i < 4; i++) {
        int k = k0 + ty + i * 8;
        tile[ty + i * 8][tx] = W[(size_t)k * Nout + n0 + tx];
    }
    __syncthreads();
#pragma unroll
    for (int i = 0; i < 4; i++) {
        int n = n0 + ty + i * 8;
        float v = tile[tx][ty + i * 8];
        __nv_bfloat16 h, l;
        split_bf16(v, h, l);
        Hi[(size_t)n * DIM + k0 + tx] = h;
        Lo[(size_t)n * DIM + k0 + tx] = l;
    }
}

// ---------------------------------------------------------------------------
// Fused per-token middle stage: RMSNorm(q,k) -> RoPE -> 16x16 scores ->
// softmax -> attn @ v -> bf16 hi/lo row-major (GEMM2 A operand).
// One block (128 threads) per token.
// ---------------------------------------------------------------------------
__global__ __launch_bounds__(128)
void attn_kernel(const float* __restrict__ qkv,
                 const float* __restrict__ fcos, const float* __restrict__ fsin,
                 const float* __restrict__ g_q, const float* __restrict__ g_k,
                 __nv_bfloat16* __restrict__ ahi, __nv_bfloat16* __restrict__ alo) {
    const int token = blockIdx.x;
    const int n_idx = token & (SEQ - 1);
    const float* row = qkv + (size_t)token * QKVDIM;

    __shared__ float sq[NHEAD][HDIM];
    __shared__ float sk[NHEAD][HDIM];
    __shared__ float sv[NHEAD][HDIM];
    __shared__ float sc[HDIM / 2], ss[HDIM / 2];
    __shared__ float sscore[NHEAD][NHEAD + 1];
    __shared__ __align__(16) float sout[DIM];

    const int tid = threadIdx.x;

    for (int i = tid; i < DIM / 4; i += 128) {
        ((float4*)&sq[0][0])[i] = ((const float4*)row)[i];
        ((float4*)&sk[0][0])[i] = ((const float4*)(row + DIM))[i];
        ((float4*)&sv[0][0])[i] = ((const float4*)(row + 2 * DIM))[i];
    }
    if (tid < HDIM / 2) {
        sc[tid] = fcos[(size_t)n_idx * (HDIM / 2) + tid];
        ss[tid] = fsin[(size_t)n_idx * (HDIM / 2) + tid];
    }
    __syncthreads();

    // RMSNorm + RoPE: 32 tasks (16 q-heads, 16 k-heads), 4 threads each.
    {
        const int task = tid >> 2;
        const int l4 = tid & 3;
        const int hh = task & (NHEAD - 1);
        float* vec = (task < NHEAD) ? sq[hh] : sk[hh];
        const float* g = (task < NHEAD) ? g_q : g_k;

        float ssum = 0.f;
        const int e0 = l4 * 16;
#pragma unroll
        for (int e = 0; e < 16; e++) {
            float v = vec[e0 + e];
            ssum += v * v;
        }
        ssum += __shfl_xor_sync(0xffffffffu, ssum, 1);
        ssum += __shfl_xor_sync(0xffffffffu, ssum, 2);
        float nrm = sqrtf(ssum) * 0.125f;   // ||x|| * d^-0.5, d=64
        float inv = 1.f / (nrm + 1e-6f);

        const int p0 = l4 * 8;
#pragma unroll
        for (int p = 0; p < 8; p++) {
            int pp = p0 + p;
            float re = vec[2 * pp] * inv * g[2 * pp];
            float im = vec[2 * pp + 1] * inv * g[2 * pp + 1];
            float cc = sc[pp], sn = ss[pp];
            vec[2 * pp]     = re * cc - im * sn;
            vec[2 * pp + 1] = re * sn + im * cc;
        }
    }
    __syncthreads();

    for (int e = tid; e < NHEAD * NHEAD; e += 128) {
        int i = e >> 4, j = e & 15;
        float a = 0.f;
#pragma unroll
        for (int dd = 0; dd < HDIM; dd++) a += sq[i][dd] * sk[j][dd];
        sscore[i][j] = a * 0.125f;
    }
    __syncthreads();

    if (tid < NHEAD) {
        float mx = -1e30f;
#pragma unroll
        for (int j = 0; j < NHEAD; j++) mx = fmaxf(mx, sscore[tid][j]);
        float sum = 0.f;
#pragma unroll
        for (int j = 0; j < NHEAD; j++) {
            float e2 = expf(sscore[tid][j] - mx);
            sscore[tid][j] = e2;
            sum += e2;
        }
        float rr = 1.f / sum;
#pragma unroll
        for (int j = 0; j < NHEAD; j++) sscore[tid][j] *= rr;
    }
    __syncthreads();

    for (int e = tid; e < DIM; e += 128) {
        int i = e >> 6, dd = e & 63;
        float a = 0.f;
#pragma unroll
        for (int j = 0; j < NHEAD; j++) a = fmaf(sscore[i][j], sv[j][dd], a);
        sout[e] = a;
    }
    __syncthreads();

    // hi/lo split, row-major write (8 consecutive elems per thread).
    {
        const int k0 = tid * 8;
        float4 f0 = *(const float4*)&sout[k0];
        float4 f1 = *(const float4*)&sout[k0 + 4];
        float v[8] = {f0.x, f0.y, f0.z, f0.w, f1.x, f1.y, f1.z, f1.w};
        union { __nv_bfloat16 b[8]; uint4 q; } H, L;
#pragma unroll
        for (int i = 0; i < 8; i++) split_bf16(v[i], H.b[i], L.b[i]);
        size_t base = ((size_t)token * DIM + k0) / 8;
        ((uint4*)ahi)[base] = H.q;
        ((uint4*)alo)[base] = L.q;
    }
}

// ---------------------------------------------------------------------------
extern "C" void kernel_launch(void* const* d_in, const int* in_sizes, int n_in,
                              void* d_out, int out_size) {
    const float* x     = (const float*)d_in[0];
    const float* fcos  = (const float*)d_in[1];
    const float* fsin  = (const float*)d_in[2];
    const float* wqkv  = (const float*)d_in[3];
    const float* gq    = (const float*)d_in[4];
    const float* gk    = (const float*)d_in[5];
    const float* wproj = (const float*)d_in[6];
    const float* bproj = (const float*)d_in[7];
    float* out = (float*)d_out;

    void *p_xhi, *p_xlo, *p_wqhi, *p_wqlo, *p_wphi, *p_wplo, *p_ahi, *p_alo, *p_qkv;
    cudaGetSymbolAddress(&p_xhi,  g_xhi);
    cudaGetSymbolAddress(&p_xlo,  g_xlo);
    cudaGetSymbolAddress(&p_wqhi, g_wqhi);
    cudaGetSymbolAddress(&p_wqlo, g_wqlo);
    cudaGetSymbolAddress(&p_wphi, g_wphi);
    cudaGetSymbolAddress(&p_wplo, g_wplo);
    cudaGetSymbolAddress(&p_ahi,  g_ahi);
    cudaGetSymbolAddress(&p_alo,  g_alo);
    cudaGetSymbolAddress(&p_qkv,  g_qkv);

    cudaFuncSetAttribute(mma_gemm<false>, cudaFuncAttributeMaxDynamicSharedMemorySize, GEMM_SMEM);
    cudaFuncSetAttribute(mma_gemm<true>,  cudaFuncAttributeMaxDynamicSharedMemorySize, GEMM_SMEM);

    // 1) split x -> bf16 hi/lo
    {
        size_t total8 = (size_t)TOKENS * DIM / 8;
        convert_A_kernel<<<(unsigned)((total8 + 255) / 256), 256>>>(
            x, (__nv_bfloat16*)p_xhi, (__nv_bfloat16*)p_xlo, total8);
    }
    // 2) transpose + split weights -> [N,K] bf16 hi/lo
    convert_W_kernel<<<dim3(QKVDIM / 32, DIM / 32), 256>>>(
        wqkv, (__nv_bfloat16*)p_wqhi, (__nv_bfloat16*)p_wqlo, QKVDIM);
    convert_W_kernel<<<dim3(DIM / 32, DIM / 32), 256>>>(
        wproj, (__nv_bfloat16*)p_wphi, (__nv_bfloat16*)p_wplo, DIM);

    // 3) qkv = x @ w_qkv
    mma_gemm<false><<<dim3(QKVDIM / BN, TOKENS / BM), 256, GEMM_SMEM>>>(
        (const __nv_bfloat16*)p_xhi, (const __nv_bfloat16*)p_xlo,
        (const __nv_bfloat16*)p_wqhi, (const __nv_bfloat16*)p_wqlo,
        nullptr, (float*)p_qkv, QKVDIM);

    // 4) fused RMSNorm+RoPE+head-mixing attention -> GEMM2 A operand (bf16 hi/lo)
    attn_kernel<<<TOKENS, 128>>>((const float*)p_qkv, fcos, fsin, gq, gk,
                                 (__nv_bfloat16*)p_ahi, (__nv_bfloat16*)p_alo);

    // 5) out = att @ w_proj + b
    mma_gemm<true><<<dim3(DIM / BN, TOKENS / BM), 256, GEMM_SMEM>>>(
        (const __nv_bfloat16*)p_ahi, (const __nv_bfloat16*)p_alo,
        (const __nv_bfloat16*)p_wphi, (const __nv_bfloat16*)p_wplo,
        bproj, out, DIM);
}

// round 5
// speedup vs baseline: 2.8926x; 1.1427x over previous
#include <cuda_runtime.h>
#include <cuda_bf16.h>
#include <stdint.h>
#include <math.h>

// Problem constants: b=4, n=4096 -> T=16384 tokens, dim=1024, heads=16, d=64
#define TOKENS 16384
#define DIM    1024
#define QKVDIM 3072
#define NHEAD  16
#define HDIM   64
#define SEQ    4096

// GEMM tiling (K is always 1024)
#define BM 128
#define BN 128
#define BK 32
#define KCHUNKS (DIM / BK)          // 32
#define STAGES 3
#define ARR_BYTES (BM * BK * 2)     // 8192 per operand array per stage
#define STAGE_BYTES (4 * ARR_BYTES) // 32768 (Ahi, Alo, Bhi, Blo)
#define GEMM_SMEM (STAGES * STAGE_BYTES)  // 98304

// ---------------------------------------------------------------------------
// Scratch (device globals; kernel_launch is allocation-free)
// ---------------------------------------------------------------------------
__device__ __align__(256) __nv_bfloat16 g_xhi [(size_t)TOKENS * DIM];
__device__ __align__(256) __nv_bfloat16 g_xlo [(size_t)TOKENS * DIM];
__device__ __align__(256) __nv_bfloat16 g_wqhi[(size_t)QKVDIM * DIM]; // [N,K]
__device__ __align__(256) __nv_bfloat16 g_wqlo[(size_t)QKVDIM * DIM];
__device__ __align__(256) __nv_bfloat16 g_wphi[(size_t)DIM * DIM];    // [N,K]
__device__ __align__(256) __nv_bfloat16 g_wplo[(size_t)DIM * DIM];
__device__ __align__(256) __nv_bfloat16 g_ahi [(size_t)TOKENS * DIM];
__device__ __align__(256) __nv_bfloat16 g_alo [(size_t)TOKENS * DIM];
__device__ __align__(256) float         g_qkv [(size_t)TOKENS * QKVDIM];

// ---------------------------------------------------------------------------
// PTX helpers (baseline sm_80+ features only — no tcgen05 on this target)
// ---------------------------------------------------------------------------
__device__ __forceinline__ uint32_t s2u(const void* p) {
    uint32_t a;
    asm("{ .reg .u64 t; cvta.to.shared.u64 t, %1; cvt.u32.u64 %0, t; }"
        : "=r"(a) : "l"(p));
    return a;
}

__device__ __forceinline__ void cp_async16(uint32_t dst, const void* gsrc) {
    asm volatile("cp.async.cg.shared.global [%0], [%1], 16;"
                 :: "r"(dst), "l"(__cvta_generic_to_global(gsrc)) : "memory");
}
__device__ __forceinline__ void cp_commit() {
    asm volatile("cp.async.commit_group;" ::: "memory");
}
__device__ __forceinline__ void cp_wait1() {
    asm volatile("cp.async.wait_group 1;" ::: "memory");
}

__device__ __forceinline__ void ldsm_x4(uint32_t& r0, uint32_t& r1,
                                        uint32_t& r2, uint32_t& r3, uint32_t addr) {
    asm volatile("ldmatrix.sync.aligned.m8n8.x4.shared.b16 {%0,%1,%2,%3}, [%4];"
                 : "=r"(r0), "=r"(r1), "=r"(r2), "=r"(r3) : "r"(addr));
}

__device__ __forceinline__ void mma16816(float* c, const uint32_t* a, const uint32_t* b) {
    asm volatile(
        "mma.sync.aligned.m16n8k16.row.col.f32.bf16.bf16.f32 "
        "{%0,%1,%2,%3}, {%4,%5,%6,%7}, {%8,%9}, {%0,%1,%2,%3};"
        : "+f"(c[0]), "+f"(c[1]), "+f"(c[2]), "+f"(c[3])
        : "r"(a[0]), "r"(a[1]), "r"(a[2]), "r"(a[3]), "r"(b[0]), "r"(b[1]));
}

__device__ __forceinline__ void split_bf16(float x, __nv_bfloat16& h, __nv_bfloat16& l) {
    h = __float2bfloat16_rn(x);
    l = __float2bfloat16_rn(x - __bfloat162float(h));
}

// Swizzled smem byte offset for a (row, 16B-unit) within a [128][BK] bf16 tile.
__device__ __forceinline__ uint32_t sw_off(int row, int u) {
    return (uint32_t)(row * 64 + (((u ^ ((row >> 1) & 3)) & 3) << 4));
}

// ---------------------------------------------------------------------------
// GEMM: C[M,N] = A @ B^T, A=[M,1024] bf16 hi/lo, B=[N,1024] bf16 hi/lo.
// 3-term split: hi*hi + hi*lo + lo*hi, fp32 accumulators.
// grid (N/128, M/128), 256 threads (8 warps, each 64x32). 2 CTAs/SM.
// ---------------------------------------------------------------------------
template <bool BIAS>
__global__ __launch_bounds__(256, 2)
void mma_gemm(const __nv_bfloat16* __restrict__ Ahi, const __nv_bfloat16* __restrict__ Alo,
              const __nv_bfloat16* __restrict__ Bhi, const __nv_bfloat16* __restrict__ Blo,
              const float* __restrict__ bias, float* __restrict__ C, int N) {
    extern __shared__ __align__(256) char smem[];
    const uint32_t sb = s2u(smem);
    const int tid = threadIdx.x;
    const int wid = tid >> 5, lane = tid & 31;
    const int m0 = blockIdx.y * BM;
    const int n0 = blockIdx.x * BN;

    const __nv_bfloat16* bases[4] = {
        Ahi + (size_t)m0 * DIM, Alo + (size_t)m0 * DIM,
        Bhi + (size_t)n0 * DIM, Blo + (size_t)n0 * DIM
    };

    // --- async stage loader: 2048 x 16B units per stage, 8 per thread ---
    auto load_stage = [&](int s, int c) {
#pragma unroll
        for (int i = 0; i < 8; i++) {
            int u = tid + i * 256;
            int arr = u >> 9;            // 0..3
            int idx = u & 511;
            int row = idx >> 2;          // 0..127
            int cu  = idx & 3;           // 16B unit within 64B row
            const char* src = (const char*)bases[arr]
                              + (size_t)row * (DIM * 2) + c * (BK * 2) + cu * 16;
            uint32_t dst = sb + s * STAGE_BYTES + arr * ARR_BYTES + sw_off(row, cu);
            cp_async16(dst, src);
        }
    };

    // prologue
#pragma unroll
    for (int s = 0; s < STAGES - 1; s++) { load_stage(s, s); cp_commit(); }

    const int wr = wid >> 2, wc = wid & 3;   // 2x4 warp grid
    const int wo = wr * 64, no = wc * 32;

    float acc[4][4][4];
#pragma unroll
    for (int mi = 0; mi < 4; mi++)
#pragma unroll
        for (int ni = 0; ni < 4; ni++)
#pragma unroll
            for (int e = 0; e < 4; e++) acc[mi][ni][e] = 0.f;

    const int la = lane & 15;

    for (int c = 0; c < KCHUNKS; c++) {
        cp_wait1();
        __syncthreads();

        const int cn = c + STAGES - 1;
        if (cn < KCHUNKS) load_stage(cn % STAGES, cn);
        cp_commit();

        const uint32_t st = sb + (c % STAGES) * STAGE_BYTES;
        const uint32_t sAh = st;
        const uint32_t sAl = st + ARR_BYTES;
        const uint32_t sBh = st + 2 * ARR_BYTES;
        const uint32_t sBl = st + 3 * ARR_BYTES;

#pragma unroll
        for (int k16 = 0; k16 < 2; k16++) {
            // B fragments for all 4 ni (hi+lo), via x4 ldmatrix pairs:
            // lane group g = lane>>3: matrix g = (row-group g>>1, k-unit g&1)
            uint32_t bh[4][2], bl[4][2];
            const int brow_lo = (lane >> 4) & 1;         // which ni within pair
            const int bu = k16 * 2 + ((lane >> 3) & 1);  // k-unit
#pragma unroll
            for (int p = 0; p < 2; p++) {
                const int row = no + (p * 2 + brow_lo) * 8 + (lane & 7);
                uint32_t off = sw_off(row, bu);
                ldsm_x4(bh[p*2][0], bh[p*2][1], bh[p*2+1][0], bh[p*2+1][1], sBh + off);
                ldsm_x4(bl[p*2][0], bl[p*2][1], bl[p*2+1][0], bl[p*2+1][1], sBl + off);
            }
            const int au = k16 * 2 + (lane >> 4);
#pragma unroll
            for (int mi = 0; mi < 4; mi++) {
                uint32_t ah[4], al[4];
                const int row = wo + mi * 16 + la;
                uint32_t off = sw_off(row, au);
                ldsm_x4(ah[0], ah[1], ah[2], ah[3], sAh + off);
                ldsm_x4(al[0], al[1], al[2], al[3], sAl + off);
#pragma unroll
                for (int ni = 0; ni < 4; ni++) mma16816(acc[mi][ni], ah, bh[ni]);
#pragma unroll
                for (int ni = 0; ni < 4; ni++) mma16816(acc[mi][ni], ah, bl[ni]);
#pragma unroll
                for (int ni = 0; ni < 4; ni++) mma16816(acc[mi][ni], al, bh[ni]);
            }
        }
    }

    // epilogue
    const int tg = lane >> 2, tq = lane & 3;
#pragma unroll
    for (int mi = 0; mi < 4; mi++) {
#pragma unroll
        for (int ni = 0; ni < 4; ni++) {
            const float* cc = acc[mi][ni];
            int col = n0 + no + ni * 8 + tq * 2;
            float bx = 0.f, by = 0.f;
            if (BIAS) { bx = bias[col]; by = bias[col + 1]; }
            size_t r0 = (size_t)(m0 + wo + mi * 16 + tg);
            float2 v0 = {cc[0] + bx, cc[1] + by};
            float2 v1 = {cc[2] + bx, cc[3] + by};
            *(float2*)(C + r0 * N + col) = v0;
            *(float2*)(C + (r0 + 8) * N + col) = v1;
        }
    }
}

// ---------------------------------------------------------------------------
// Conversions
// ---------------------------------------------------------------------------
__global__ void convert_A_kernel(const float* __restrict__ X,
                                 __nv_bfloat16* __restrict__ Hi,
                                 __nv_bfloat16* __restrict__ Lo, size_t total8) {
    size_t t = (size_t)blockIdx.x * blockDim.x + threadIdx.x;
    if (t >= total8) return;
    const float* src = X + t * 8;
    float4 f0 = *(const float4*)src;
    float4 f1 = *(const float4*)(src + 4);
    float v[8] = {f0.x, f0.y, f0.z, f0.w, f1.x, f1.y, f1.z, f1.w};
    union { __nv_bfloat16 b[8]; uint4 q; } H, L;
#pragma unroll
    for (int i = 0; i < 8; i++) split_bf16(v[i], H.b[i], L.b[i]);
    ((uint4*)Hi)[t] = H.q;
    ((uint4*)Lo)[t] = L.q;
}

__global__ void convert_W_kernel(const float* __restrict__ W,
                                 __nv_bfloat16* __restrict__ Hi,
                                 __nv_bfloat16* __restrict__ Lo, int Nout) {
    __shared__ float tile[32][33];
    const int tx = threadIdx.x & 31, ty = threadIdx.x >> 5;   // 256 threads
    const int n0 = blockIdx.x * 32, k0 = blockIdx.y * 32;
#pragma unroll
    for (int i = 0; i < 4; i++) {
        int k = k0 + ty + i * 8;
        tile[ty + i * 8][tx] = W[(size_t)k * Nout + n0 + tx];
    }
    __syncthreads();
#pragma unroll
    for (int i = 0; i < 4; i++) {
        int n = n0 + ty + i * 8;
        float v = tile[tx][ty + i * 8];
        __nv_bfloat16 h, l;
        split_bf16(v, h, l);
        Hi[(size_t)n * DIM + k0 + tx] = h;
        Lo[(size_t)n * DIM + k0 + tx] = l;
    }
}

// ---------------------------------------------------------------------------
// Fused per-token middle stage (unchanged from passing R4 kernel)
// ---------------------------------------------------------------------------
__global__ __launch_bounds__(128)
void attn_kernel(const float* __restrict__ qkv,
                 const float* __restrict__ fcos, const float* __restrict__ fsin,
                 const float* __restrict__ g_q, const float* __restrict__ g_k,
                 __nv_bfloat16* __restrict__ ahi, __nv_bfloat16* __restrict__ alo) {
    const int token = blockIdx.x;
    const int n_idx = token & (SEQ - 1);
    const float* row = qkv + (size_t)token * QKVDIM;

    __shared__ float sq[NHEAD][HDIM];
    __shared__ float sk[NHEAD][HDIM];
    __shared__ float sv[NHEAD][HDIM];
    __shared__ float sc[HDIM / 2], ss[HDIM / 2];
    __shared__ float sscore[NHEAD][NHEAD + 1];
    __shared__ __align__(16) float sout[DIM];

    const int tid = threadIdx.x;

    for (int i = tid; i < DIM / 4; i += 128) {
        ((float4*)&sq[0][0])[i] = ((const float4*)row)[i];
        ((float4*)&sk[0][0])[i] = ((const float4*)(row + DIM))[i];
        ((float4*)&sv[0][0])[i] = ((const float4*)(row + 2 * DIM))[i];
    }
    if (tid < HDIM / 2) {
        sc[tid] = fcos[(size_t)n_idx * (HDIM / 2) + tid];
        ss[tid] = fsin[(size_t)n_idx * (HDIM / 2) + tid];
    }
    __syncthreads();

    {
        const int task = tid >> 2;
        const int l4 = tid & 3;
        const int hh = task & (NHEAD - 1);
        float* vec = (task < NHEAD) ? sq[hh] : sk[hh];
        const float* g = (task < NHEAD) ? g_q : g_k;

        float ssum = 0.f;
        const int e0 = l4 * 16;
#pragma unroll
        for (int e = 0; e < 16; e++) {
            float v = vec[e0 + e];
            ssum += v * v;
        }
        ssum += __shfl_xor_sync(0xffffffffu, ssum, 1);
        ssum += __shfl_xor_sync(0xffffffffu, ssum, 2);
        float nrm = sqrtf(ssum) * 0.125f;   // ||x|| * d^-0.5, d=64
        float inv = 1.f / (nrm + 1e-6f);

        const int p0 = l4 * 8;
#pragma unroll
        for (int p = 0; p < 8; p++) {
            int pp = p0 + p;
            float re = vec[2 * pp] * inv * g[2 * pp];
            float im = vec[2 * pp + 1] * inv * g[2 * pp + 1];
            float cc = sc[pp], sn = ss[pp];
            vec[2 * pp]     = re * cc - im * sn;
            vec[2 * pp + 1] = re * sn + im * cc;
        }
    }
    __syncthreads();

    for (int e = tid; e < NHEAD * NHEAD; e += 128) {
        int i = e >> 4, j = e & 15;
        float a = 0.f;
#pragma unroll
        for (int dd = 0; dd < HDIM; dd++) a += sq[i][dd] * sk[j][dd];
        sscore[i][j] = a * 0.125f;
    }
    __syncthreads();

    if (tid < NHEAD) {
        float mx = -1e30f;
#pragma unroll
        for (int j = 0; j < NHEAD; j++) mx = fmaxf(mx, sscore[tid][j]);
        float sum = 0.f;
#pragma unroll
        for (int j = 0; j < NHEAD; j++) {
            float e2 = expf(sscore[tid][j] - mx);
            sscore[tid][j] = e2;
            sum += e2;
        }
        float rr = 1.f / sum;
#pragma unroll
        for (int j = 0; j < NHEAD; j++) sscore[tid][j] *= rr;
    }
    __syncthreads();

    for (int e = tid; e < DIM; e += 128) {
        int i = e >> 6, dd = e & 63;
        float a = 0.f;
#pragma unroll
        for (int j = 0; j < NHEAD; j++) a = fmaf(sscore[i][j], sv[j][dd], a);
        sout[e] = a;
    }
    __syncthreads();

    {
        const int k0 = tid * 8;
        float4 f0 = *(const float4*)&sout[k0];
        float4 f1 = *(const float4*)&sout[k0 + 4];
        float v[8] = {f0.x, f0.y, f0.z, f0.w, f1.x, f1.y, f1.z, f1.w};
        union { __nv_bfloat16 b[8]; uint4 q; } H, L;
#pragma unroll
        for (int i = 0; i < 8; i++) split_bf16(v[i], H.b[i], L.b[i]);
        size_t base = ((size_t)token * DIM + k0) / 8;
        ((uint4*)ahi)[base] = H.q;
        ((uint4*)alo)[base] = L.q;
    }
}

// ---------------------------------------------------------------------------
extern "C" void kernel_launch(void* const* d_in, const int* in_sizes, int n_in,
                              void* d_out, int out_size) {
    const float* x     = (const float*)d_in[0];
    const float* fcos  = (const float*)d_in[1];
    const float* fsin  = (const float*)d_in[2];
    const float* wqkv  = (const float*)d_in[3];
    const float* gq    = (const float*)d_in[4];
    const float* gk    = (const float*)d_in[5];
    const float* wproj = (const float*)d_in[6];
    const float* bproj = (const float*)d_in[7];
    float* out = (float*)d_out;

    void *p_xhi, *p_xlo, *p_wqhi, *p_wqlo, *p_wphi, *p_wplo, *p_ahi, *p_alo, *p_qkv;
    cudaGetSymbolAddress(&p_xhi,  g_xhi);
    cudaGetSymbolAddress(&p_xlo,  g_xlo);
    cudaGetSymbolAddress(&p_wqhi, g_wqhi);
    cudaGetSymbolAddress(&p_wqlo, g_wqlo);
    cudaGetSymbolAddress(&p_wphi, g_wphi);
    cudaGetSymbolAddress(&p_wplo, g_wplo);
    cudaGetSymbolAddress(&p_ahi,  g_ahi);
    cudaGetSymbolAddress(&p_alo,  g_alo);
    cudaGetSymbolAddress(&p_qkv,  g_qkv);

    cudaFuncSetAttribute(mma_gemm<false>, cudaFuncAttributeMaxDynamicSharedMemorySize, GEMM_SMEM);
    cudaFuncSetAttribute(mma_gemm<true>,  cudaFuncAttributeMaxDynamicSharedMemorySize, GEMM_SMEM);

    {
        size_t total8 = (size_t)TOKENS * DIM / 8;
        convert_A_kernel<<<(unsigned)((total8 + 255) / 256), 256>>>(
            x, (__nv_bfloat16*)p_xhi, (__nv_bfloat16*)p_xlo, total8);
    }
    convert_W_kernel<<<dim3(QKVDIM / 32, DIM / 32), 256>>>(
        wqkv, (__nv_bfloat16*)p_wqhi, (__nv_bfloat16*)p_wqlo, QKVDIM);
    convert_W_kernel<<<dim3(DIM / 32, DIM / 32), 256>>>(
        wproj, (__nv_bfloat16*)p_wphi, (__nv_bfloat16*)p_wplo, DIM);

    mma_gemm<false><<<dim3(QKVDIM / BN, TOKENS / BM), 256, GEMM_SMEM>>>(
        (const __nv_bfloat16*)p_xhi, (const __nv_bfloat16*)p_xlo,
        (const __nv_bfloat16*)p_wqhi, (const __nv_bfloat16*)p_wqlo,
        nullptr, (float*)p_qkv, QKVDIM);

    attn_kernel<<<TOKENS, 128>>>((const float*)p_qkv, fcos, fsin, gq, gk,
                                 (__nv_bfloat16*)p_ahi, (__nv_bfloat16*)p_alo);

    mma_gemm<true><<<dim3(DIM / BN, TOKENS / BM), 256, GEMM_SMEM>>>(
        (const __nv_bfloat16*)p_ahi, (const __nv_bfloat16*)p_alo,
        (const __nv_bfloat16*)p_wphi, (const __nv_bfloat16*)p_wplo,
        bproj, out, DIM);
}

// round 7
// speedup vs baseline: 3.5956x; 1.2430x over previous
#include <cuda_runtime.h>
#include <cuda_bf16.h>
#include <cuda_fp16.h>
#include <stdint.h>
#include <math.h>

// Problem constants: b=4, n=4096 -> T=16384 tokens, dim=1024, heads=16, d=64
#define TOKENS 16384
#define DIM    1024
#define QKVDIM 3072
#define NHEAD  16
#define HDIM   64
#define SEQ    4096

// GEMM tiling (K is always 1024)
#define BM 128
#define BN 128
#define BK 32
#define KCHUNKS (DIM / BK)          // 32
#define STAGES 4
#define ARR_BYTES (BM * BK * 2)     // 8192 per operand array per stage
#define STAGE_BYTES (3 * ARR_BYTES) // 24576 (Ahi, Alo, Bhi)
#define GEMM_SMEM (STAGES * STAGE_BYTES)  // 98304

// ---------------------------------------------------------------------------
// Scratch (device globals; kernel_launch is allocation-free)
// ---------------------------------------------------------------------------
__device__ __align__(256) __half g_xhi [(size_t)TOKENS * DIM];
__device__ __align__(256) __half g_xlo [(size_t)TOKENS * DIM];
__device__ __align__(256) __half g_wqhi[(size_t)QKVDIM * DIM]; // [N,K]
__device__ __align__(256) __half g_wphi[(size_t)DIM * DIM];    // [N,K]
__device__ __align__(256) __half g_ahi [(size_t)TOKENS * DIM];
__device__ __align__(256) __half g_alo [(size_t)TOKENS * DIM];
__device__ __align__(256) float  g_qkv [(size_t)TOKENS * QKVDIM];

// ---------------------------------------------------------------------------
// PTX helpers (baseline sm_80+ features only — tcgen05 unavailable on target)
// ---------------------------------------------------------------------------
__device__ __forceinline__ uint32_t s2u(const void* p) {
    uint32_t a;
    asm("{ .reg .u64 t; cvta.to.shared.u64 t, %1; cvt.u32.u64 %0, t; }"
        : "=r"(a) : "l"(p));
    return a;
}

__device__ __forceinline__ void cp_async16(uint32_t dst, const void* gsrc) {
    asm volatile("cp.async.cg.shared.global [%0], [%1], 16;"
                 :: "r"(dst), "l"(__cvta_generic_to_global(gsrc)) : "memory");
}
__device__ __forceinline__ void cp_commit() {
    asm volatile("cp.async.commit_group;" ::: "memory");
}
__device__ __forceinline__ void cp_wait2() {
    asm volatile("cp.async.wait_group 2;" ::: "memory");
}

__device__ __forceinline__ void ldsm_x4(uint32_t& r0, uint32_t& r1,
                                        uint32_t& r2, uint32_t& r3, uint32_t addr) {
    asm volatile("ldmatrix.sync.aligned.m8n8.x4.shared.b16 {%0,%1,%2,%3}, [%4];"
                 : "=r"(r0), "=r"(r1), "=r"(r2), "=r"(r3) : "r"(addr));
}

__device__ __forceinline__ void mma16816(float* c, const uint32_t* a, const uint32_t* b) {
    asm volatile(
        "mma.sync.aligned.m16n8k16.row.col.f32.f16.f16.f32 "
        "{%0,%1,%2,%3}, {%4,%5,%6,%7}, {%8,%9}, {%0,%1,%2,%3};"
        : "+f"(c[0]), "+f"(c[1]), "+f"(c[2]), "+f"(c[3])
        : "r"(a[0]), "r"(a[1]), "r"(a[2]), "r"(a[3]), "r"(b[0]), "r"(b[1]));
}

__device__ __forceinline__ void split_f16(float x, __half& h, __half& l) {
    h = __float2half_rn(x);
    l = __float2half_rn(x - __half2float(h));
}

// Swizzled smem byte offset for a (row, 16B-unit) within a [128][BK] f16 tile.
__device__ __forceinline__ uint32_t sw_off(int row, int u) {
    return (uint32_t)(row * 64 + (((u ^ ((row >> 1) & 3)) & 3) << 4));
}

// ---------------------------------------------------------------------------
// GEMM: C[M,N] = A @ B^T, A=[M,1024] fp16 hi/lo (exact split), B=[N,1024] fp16 hi.
// 2-pass: C = Ahi*Bhi + Alo*Bhi  (== (Ahi+Alo)*Bhi; error only from B rounding)
// grid (N/128, M/128), 256 threads (8 warps, each 64x32). 2 CTAs/SM, 4 stages.
// ---------------------------------------------------------------------------
template <bool BIAS>
__global__ __launch_bounds__(256, 2)
void mma_gemm(const __half* __restrict__ Ahi, const __half* __restrict__ Alo,
              const __half* __restrict__ Bhi,
              const float* __restrict__ bias, float* __restrict__ C, int N) {
    extern __shared__ __align__(256) char smem[];
    const uint32_t sb = s2u(smem);
    const int tid = threadIdx.x;
    const int wid = tid >> 5, lane = tid & 31;
    const int m0 = blockIdx.y * BM;
    const int n0 = blockIdx.x * BN;

    const __half* bases[3] = {
        Ahi + (size_t)m0 * DIM, Alo + (size_t)m0 * DIM,
        Bhi + (size_t)n0 * DIM
    };

    // --- async stage loader: 1536 x 16B units per stage, 6 per thread ---
    auto load_stage = [&](int s, int c) {
#pragma unroll
        for (int i = 0; i < 6; i++) {
            int u = tid + i * 256;
            int arr = u >> 9;            // 0..2
            int idx = u & 511;
            int row = idx >> 2;          // 0..127
            int cu  = idx & 3;           // 16B unit within 64B row
            const char* src = (const char*)bases[arr]
                              + (size_t)row * (DIM * 2) + c * (BK * 2) + cu * 16;
            uint32_t dst = sb + s * STAGE_BYTES + arr * ARR_BYTES + sw_off(row, cu);
            cp_async16(dst, src);
        }
    };

    // prologue: fill 3 of 4 stages
#pragma unroll
    for (int s = 0; s < STAGES - 1; s++) { load_stage(s, s); cp_commit(); }

    const int wr = wid >> 2, wc = wid & 3;   // 2x4 warp grid
    const int wo = wr * 64, no = wc * 32;

    float acc[4][4][4];
#pragma unroll
    for (int mi = 0; mi < 4; mi++)
#pragma unroll
        for (int ni = 0; ni < 4; ni++)
#pragma unroll
            for (int e = 0; e < 4; e++) acc[mi][ni][e] = 0.f;

    const int la = lane & 15;

    for (int c = 0; c < KCHUNKS; c++) {
        cp_wait2();
        __syncthreads();

        const int cn = c + STAGES - 1;
        if (cn < KCHUNKS) load_stage(cn % STAGES, cn);
        cp_commit();

        const uint32_t st = sb + (c % STAGES) * STAGE_BYTES;
        const uint32_t sAh = st;
        const uint32_t sAl = st + ARR_BYTES;
        const uint32_t sBh = st + 2 * ARR_BYTES;

#pragma unroll
        for (int k16 = 0; k16 < 2; k16++) {
            // B hi fragments for all 4 ni via x4 ldmatrix pairs.
            uint32_t bh[4][2];
            const int brow_lo = (lane >> 4) & 1;         // which ni within pair
            const int bu = k16 * 2 + ((lane >> 3) & 1);  // k-unit
#pragma unroll
            for (int p = 0; p < 2; p++) {
                const int row = no + (p * 2 + brow_lo) * 8 + (lane & 7);
                uint32_t off = sw_off(row, bu);
                ldsm_x4(bh[p*2][0], bh[p*2][1], bh[p*2+1][0], bh[p*2+1][1], sBh + off);
            }
            const int au = k16 * 2 + (lane >> 4);
#pragma unroll
            for (int mi = 0; mi < 4; mi++) {
                uint32_t ah[4], al[4];
                const int row = wo + mi * 16 + la;
                uint32_t off = sw_off(row, au);
                ldsm_x4(ah[0], ah[1], ah[2], ah[3], sAh + off);
                ldsm_x4(al[0], al[1], al[2], al[3], sAl + off);
#pragma unroll
                for (int ni = 0; ni < 4; ni++) mma16816(acc[mi][ni], ah, bh[ni]);
#pragma unroll
                for (int ni = 0; ni < 4; ni++) mma16816(acc[mi][ni], al, bh[ni]);
            }
        }
    }

    // epilogue
    const int tg = lane >> 2, tq = lane & 3;
#pragma unroll
    for (int mi = 0; mi < 4; mi++) {
#pragma unroll
        for (int ni = 0; ni < 4; ni++) {
            const float* cc = acc[mi][ni];
            int col = n0 + no + ni * 8 + tq * 2;
            float bx = 0.f, by = 0.f;
            if (BIAS) { bx = bias[col]; by = bias[col + 1]; }
            size_t r0 = (size_t)(m0 + wo + mi * 16 + tg);
            float2 v0 = {cc[0] + bx, cc[1] + by};
            float2 v1 = {cc[2] + bx, cc[3] + by};
            *(float2*)(C + r0 * N + col) = v0;
            *(float2*)(C + (r0 + 8) * N + col) = v1;
        }
    }
}

// ---------------------------------------------------------------------------
// Conversions
// ---------------------------------------------------------------------------
__global__ void convert_A_kernel(const float* __restrict__ X,
                                 __half* __restrict__ Hi,
                                 __half* __restrict__ Lo, size_t total8) {
    size_t t = (size_t)blockIdx.x * blockDim.x + threadIdx.x;
    if (t >= total8) return;
    const float* src = X + t * 8;
    float4 f0 = *(const float4*)src;
    float4 f1 = *(const float4*)(src + 4);
    float v[8] = {f0.x, f0.y, f0.z, f0.w, f1.x, f1.y, f1.z, f1.w};
    union { __half b[8]; uint4 q; } H, L;
#pragma unroll
    for (int i = 0; i < 8; i++) split_f16(v[i], H.b[i], L.b[i]);
    ((uint4*)Hi)[t] = H.q;
    ((uint4*)Lo)[t] = L.q;
}

// W fp32 [1024, Nout] -> transposed fp16 (hi only) [Nout, 1024] via smem tile.
__global__ void convert_W_kernel(const float* __restrict__ W,
                                 __half* __restrict__ Hi, int Nout) {
    __shared__ float tile[32][33];
    const int tx = threadIdx.x & 31, ty = threadIdx.x >> 5;   // 256 threads
    const int n0 = blockIdx.x * 32, k0 = blockIdx.y * 32;
#pragma unroll
    for (int i = 0; i < 4; i++) {
        int k = k0 + ty + i * 8;
        tile[ty + i * 8][tx] = W[(size_t)k * Nout + n0 + tx];
    }
    __syncthreads();
#pragma unroll
    for (int i = 0; i < 4; i++) {
        int n = n0 + ty + i * 8;
        Hi[(size_t)n * DIM + k0 + tx] = __float2half_rn(tile[tx][ty + i * 8]);
    }
}

// ---------------------------------------------------------------------------
// Fused per-token middle stage: RMSNorm(q,k) -> RoPE -> 16x16 scores ->
// softmax -> attn @ v -> fp16 hi/lo row-major (GEMM2 A operand).
// 256 threads per block; 2 tokens per block (128 threads each).
// ---------------------------------------------------------------------------
__global__ __launch_bounds__(256)
void attn_kernel(const float* __restrict__ qkv,
                 const float* __restrict__ fcos, const float* __restrict__ fsin,
                 const float* __restrict__ g_q, const float* __restrict__ g_k,
                 __half* __restrict__ ahi, __half* __restrict__ alo) {
    const int g = threadIdx.x >> 7;        // token slot within block
    const int t = threadIdx.x & 127;
    const int token = blockIdx.x * 2 + g;
    const int n_idx = token & (SEQ - 1);
    const float* row = qkv + (size_t)token * QKVDIM;

    __shared__ float sq[2][NHEAD][HDIM];
    __shared__ float sk[2][NHEAD][HDIM];
    __shared__ float sv[2][NHEAD][HDIM];
    __shared__ float sc[2][HDIM / 2], ss[2][HDIM / 2];
    __shared__ float sscore[2][NHEAD][NHEAD + 1];
    __shared__ __align__(16) float sout[2][DIM];

    for (int i = t; i < DIM / 4; i += 128) {
        ((float4*)&sq[g][0][0])[i] = ((const float4*)row)[i];
        ((float4*)&sk[g][0][0])[i] = ((const float4*)(row + DIM))[i];
        ((float4*)&sv[g][0][0])[i] = ((const float4*)(row + 2 * DIM))[i];
    }
    if (t < HDIM / 2) {
        sc[g][t] = fcos[(size_t)n_idx * (HDIM / 2) + t];
        ss[g][t] = fsin[(size_t)n_idx * (HDIM / 2) + t];
    }
    __syncthreads();

    // RMSNorm + RoPE: 32 tasks (16 q-heads, 16 k-heads), 4 threads each.
    {
        const int task = t >> 2;
        const int l4 = t & 3;
        const int hh = task & (NHEAD - 1);
        float* vec = (task < NHEAD) ? sq[g][hh] : sk[g][hh];
        const float* gg = (task < NHEAD) ? g_q : g_k;

        float ssum = 0.f;
        const int e0 = l4 * 16;
#pragma unroll
        for (int e = 0; e < 16; e++) {
            float v = vec[e0 + e];
            ssum += v * v;
        }
        ssum += __shfl_xor_sync(0xffffffffu, ssum, 1);
        ssum += __shfl_xor_sync(0xffffffffu, ssum, 2);
        float nrm = sqrtf(ssum) * 0.125f;   // ||x|| * d^-0.5, d=64
        float inv = 1.f / (nrm + 1e-6f);

        const int p0 = l4 * 8;
#pragma unroll
        for (int p = 0; p < 8; p++) {
            int pp = p0 + p;
            float re = vec[2 * pp] * inv * gg[2 * pp];
            float im = vec[2 * pp + 1] * inv * gg[2 * pp + 1];
            float cc = sc[g][pp], sn = ss[g][pp];
            vec[2 * pp]     = re * cc - im * sn;
            vec[2 * pp + 1] = re * sn + im * cc;
        }
    }
    __syncthreads();

    for (int e = t; e < NHEAD * NHEAD; e += 128) {
        int i = e >> 4, j = e & 15;
        float a = 0.f;
#pragma unroll
        for (int dd = 0; dd < HDIM; dd++) a += sq[g][i][dd] * sk[g][j][dd];
        sscore[g][i][j] = a * 0.125f;
    }
    __syncthreads();

    if (t < NHEAD) {
        float mx = -1e30f;
#pragma unroll
        for (int j = 0; j < NHEAD; j++) mx = fmaxf(mx, sscore[g][t][j]);
        float sum = 0.f;
#pragma unroll
        for (int j = 0; j < NHEAD; j++) {
            float e2 = expf(sscore[g][t][j] - mx);
            sscore[g][t][j] = e2;
            sum += e2;
        }
        float rr = 1.f / sum;
#pragma unroll
        for (int j = 0; j < NHEAD; j++) sscore[g][t][j] *= rr;
    }
    __syncthreads();

    for (int e = t; e < DIM; e += 128) {
        int i = e >> 6, dd = e & 63;
        float a = 0.f;
#pragma unroll
        for (int j = 0; j < NHEAD; j++) a = fmaf(sscore[g][i][j], sv[g][j][dd], a);
        sout[g][e] = a;
    }
    __syncthreads();

    // fp16 hi/lo split, row-major write (8 consecutive elems per thread).
    {
        const int k0 = t * 8;
        float4 f0 = *(const float4*)&sout[g][k0];
        float4 f1 = *(const float4*)&sout[g][k0 + 4];
        float v[8] = {f0.x, f0.y, f0.z, f0.w, f1.x, f1.y, f1.z, f1.w};
        union { __half b[8]; uint4 q; } H, L;
#pragma unroll
        for (int i = 0; i < 8; i++) split_f16(v[i], H.b[i], L.b[i]);
        size_t base = ((size_t)token * DIM + k0) / 8;
        ((uint4*)ahi)[base] = H.q;
        ((uint4*)alo)[base] = L.q;
    }
}

// ---------------------------------------------------------------------------
extern "C" void kernel_launch(void* const* d_in, const int* in_sizes, int n_in,
                              void* d_out, int out_size) {
    const float* x     = (const float*)d_in[0];
    const float* fcos  = (const float*)d_in[1];
    const float* fsin  = (const float*)d_in[2];
    const float* wqkv  = (const float*)d_in[3];
    const float* gq    = (const float*)d_in[4];
    const float* gk    = (const float*)d_in[5];
    const float* wproj = (const float*)d_in[6];
    const float* bproj = (const float*)d_in[7];
    float* out = (float*)d_out;

    void *p_xhi, *p_xlo, *p_wqhi, *p_wphi, *p_ahi, *p_alo, *p_qkv;
    cudaGetSymbolAddress(&p_xhi,  g_xhi);
    cudaGetSymbolAddress(&p_xlo,  g_xlo);
    cudaGetSymbolAddress(&p_wqhi, g_wqhi);
    cudaGetSymbolAddress(&p_wphi, g_wphi);
    cudaGetSymbolAddress(&p_ahi,  g_ahi);
    cudaGetSymbolAddress(&p_alo,  g_alo);
    cudaGetSymbolAddress(&p_qkv,  g_qkv);

    cudaFuncSetAttribute(mma_gemm<false>, cudaFuncAttributeMaxDynamicSharedMemorySize, GEMM_SMEM);
    cudaFuncSetAttribute(mma_gemm<true>,  cudaFuncAttributeMaxDynamicSharedMemorySize, GEMM_SMEM);

    {
        size_t total8 = (size_t)TOKENS * DIM / 8;
        convert_A_kernel<<<(unsigned)((total8 + 255) / 256), 256>>>(
            x, (__half*)p_xhi, (__half*)p_xlo, total8);
    }
    convert_W_kernel<<<dim3(QKVDIM / 32, DIM / 32), 256>>>(
        wqkv, (__half*)p_wqhi, QKVDIM);
    convert_W_kernel<<<dim3(DIM / 32, DIM / 32), 256>>>(
        wproj, (__half*)p_wphi, DIM);

    // qkv = x @ w_qkv
    mma_gemm<false><<<dim3(QKVDIM / BN, TOKENS / BM), 256, GEMM_SMEM>>>(
        (const __half*)p_xhi, (const __half*)p_xlo,
        (const __half*)p_wqhi, nullptr, (float*)p_qkv, QKVDIM);

    // fused RMSNorm+RoPE+head-mixing attention -> GEMM2 A operand (fp16 hi/lo)
    attn_kernel<<<TOKENS / 2, 256>>>((const float*)p_qkv, fcos, fsin, gq, gk,
                                     (__half*)p_ahi, (__half*)p_alo);

    // out = att @ w_proj + b
    mma_gemm<true><<<dim3(DIM / BN, TOKENS / BM), 256, GEMM_SMEM>>>(
        (const __half*)p_ahi, (const __half*)p_alo,
        (const __half*)p_wphi, bproj, out, DIM);
}

// round 8
// speedup vs baseline: 3.9418x; 1.0963x over previous
#include <cuda_runtime.h>
#include <cuda_bf16.h>
#include <cuda_fp16.h>
#include <stdint.h>
#include <math.h>

// Problem constants: b=4, n=4096 -> T=16384 tokens, dim=1024, heads=16, d=64
#define TOKENS 16384
#define DIM    1024
#define QKVDIM 3072
#define NHEAD  16
#define HDIM   64
#define SEQ    4096

// GEMM tiling (K is always 1024)
#define BM 128
#define BN 128
#define BK 64
#define KCHUNKS (DIM / BK)          // 16
#define STAGES 2
#define ARR_BYTES (BM * BK * 2)     // 16384 per operand array per stage
#define STAGE_BYTES (3 * ARR_BYTES) // 49152 (Ahi, Alo, Bhi)
#define GEMM_SMEM (STAGES * STAGE_BYTES)  // 98304

// ---------------------------------------------------------------------------
// Scratch (device globals; kernel_launch is allocation-free)
// ---------------------------------------------------------------------------
__device__ __align__(256) __half g_xhi [(size_t)TOKENS * DIM];
__device__ __align__(256) __half g_xlo [(size_t)TOKENS * DIM];
__device__ __align__(256) __half g_wqhi[(size_t)QKVDIM * DIM]; // [N,K]
__device__ __align__(256) __half g_wphi[(size_t)DIM * DIM];    // [N,K]
__device__ __align__(256) __half g_ahi [(size_t)TOKENS * DIM];
__device__ __align__(256) __half g_alo [(size_t)TOKENS * DIM];
__device__ __align__(256) float  g_qkv [(size_t)TOKENS * QKVDIM];

// ---------------------------------------------------------------------------
// PTX helpers (baseline sm_80+ features only — tcgen05 unavailable on target)
// ---------------------------------------------------------------------------
__device__ __forceinline__ uint32_t s2u(const void* p) {
    uint32_t a;
    asm("{ .reg .u64 t; cvta.to.shared.u64 t, %1; cvt.u32.u64 %0, t; }"
        : "=r"(a) : "l"(p));
    return a;
}

__device__ __forceinline__ void cp_async16(uint32_t dst, const void* gsrc) {
    asm volatile("cp.async.cg.shared.global [%0], [%1], 16;"
                 :: "r"(dst), "l"(__cvta_generic_to_global(gsrc)) : "memory");
}
__device__ __forceinline__ void cp_commit() {
    asm volatile("cp.async.commit_group;" ::: "memory");
}
__device__ __forceinline__ void cp_wait0() {
    asm volatile("cp.async.wait_group 0;" ::: "memory");
}

__device__ __forceinline__ void ldsm_x4(uint32_t& r0, uint32_t& r1,
                                        uint32_t& r2, uint32_t& r3, uint32_t addr) {
    asm volatile("ldmatrix.sync.aligned.m8n8.x4.shared.b16 {%0,%1,%2,%3}, [%4];"
                 : "=r"(r0), "=r"(r1), "=r"(r2), "=r"(r3) : "r"(addr));
}

__device__ __forceinline__ void mma16816(float* c, const uint32_t* a, const uint32_t* b) {
    asm volatile(
        "mma.sync.aligned.m16n8k16.row.col.f32.f16.f16.f32 "
        "{%0,%1,%2,%3}, {%4,%5,%6,%7}, {%8,%9}, {%0,%1,%2,%3};"
        : "+f"(c[0]), "+f"(c[1]), "+f"(c[2]), "+f"(c[3])
        : "r"(a[0]), "r"(a[1]), "r"(a[2]), "r"(a[3]), "r"(b[0]), "r"(b[1]));
}

__device__ __forceinline__ void split_f16(float x, __half& h, __half& l) {
    h = __float2half_rn(x);
    l = __float2half_rn(x - __half2float(h));
}

// Swizzled smem byte offset for a (row, 16B-unit) within a [128][64] f16 tile.
// Row = 128 bytes = 8 units; phys unit = u ^ (row & 7) -> conflict-free for
// both cp.async row writes and ldmatrix 8-row column reads.
__device__ __forceinline__ uint32_t sw_off(int row, int u) {
    return (uint32_t)(row * 128 + (((u ^ (row & 7)) & 7) << 4));
}

// ---------------------------------------------------------------------------
// GEMM: C[M,N] = A @ B^T, A=[M,1024] fp16 hi/lo (exact split), B=[N,1024] fp16.
// 2-pass: C = Ahi*Bhi + Alo*Bhi (== (Ahi+Alo)*Bhi; error only from B rounding)
// grid (N/128, M/128), 256 threads (8 warps, each 64x32). 2 CTAs/SM,
// BK=64 double-buffered (one barrier per 128 MMAs/warp).
// ---------------------------------------------------------------------------
template <bool BIAS>
__global__ __launch_bounds__(256, 2)
void mma_gemm(const __half* __restrict__ Ahi, const __half* __restrict__ Alo,
              const __half* __restrict__ Bhi,
              const float* __restrict__ bias, float* __restrict__ C, int N) {
    extern __shared__ __align__(256) char smem[];
    const uint32_t sb = s2u(smem);
    const int tid = threadIdx.x;
    const int wid = tid >> 5, lane = tid & 31;
    const int m0 = blockIdx.y * BM;
    const int n0 = blockIdx.x * BN;

    const __half* bases[3] = {
        Ahi + (size_t)m0 * DIM, Alo + (size_t)m0 * DIM,
        Bhi + (size_t)n0 * DIM
    };

    // --- async stage loader: 3072 x 16B units per stage, 12 per thread ---
    auto load_stage = [&](int s, int c) {
#pragma unroll
        for (int i = 0; i < 12; i++) {
            int u = tid + i * 256;
            int arr = u >> 10;           // 0..2
            int idx = u & 1023;
            int row = idx >> 3;          // 0..127
            int cu  = idx & 7;           // 16B unit within 128B row
            const char* src = (const char*)bases[arr]
                              + (size_t)row * (DIM * 2) + c * (BK * 2) + cu * 16;
            uint32_t dst = sb + s * STAGE_BYTES + arr * ARR_BYTES + sw_off(row, cu);
            cp_async16(dst, src);
        }
    };

    // prologue: stage 0
    load_stage(0, 0);
    cp_commit();

    const int wr = wid >> 2, wc = wid & 3;   // 2x4 warp grid
    const int wo = wr * 64, no = wc * 32;

    float acc[4][4][4];
#pragma unroll
    for (int mi = 0; mi < 4; mi++)
#pragma unroll
        for (int ni = 0; ni < 4; ni++)
#pragma unroll
            for (int e = 0; e < 4; e++) acc[mi][ni][e] = 0.f;

    const int la = lane & 15;

    for (int c = 0; c < KCHUNKS; c++) {
        cp_wait0();
        __syncthreads();
        // All warps finished computing chunk c-1 (they passed this barrier),
        // so buffer (c+1)&1 is free to refill while we compute chunk c.
        const int cn = c + 1;
        if (cn < KCHUNKS) { load_stage(cn & 1, cn); cp_commit(); }

        const uint32_t st = sb + (c & 1) * STAGE_BYTES;
        const uint32_t sAh = st;
        const uint32_t sAl = st + ARR_BYTES;
        const uint32_t sBh = st + 2 * ARR_BYTES;

#pragma unroll
        for (int k16 = 0; k16 < 4; k16++) {
            // B hi fragments for all 4 ni via x4 ldmatrix pairs.
            uint32_t bh[4][2];
            const int brow_lo = (lane >> 4) & 1;         // which ni within pair
            const int bu = k16 * 2 + ((lane >> 3) & 1);  // k-unit
#pragma unroll
            for (int p = 0; p < 2; p++) {
                const int row = no + (p * 2 + brow_lo) * 8 + (lane & 7);
                uint32_t off = sw_off(row, bu);
                ldsm_x4(bh[p*2][0], bh[p*2][1], bh[p*2+1][0], bh[p*2+1][1], sBh + off);
            }
            const int au = k16 * 2 + (lane >> 4);
#pragma unroll
            for (int mi = 0; mi < 4; mi++) {
                uint32_t ah[4], al[4];
                const int row = wo + mi * 16 + la;
                uint32_t off = sw_off(row, au);
                ldsm_x4(ah[0], ah[1], ah[2], ah[3], sAh + off);
                ldsm_x4(al[0], al[1], al[2], al[3], sAl + off);
#pragma unroll
                for (int ni = 0; ni < 4; ni++) mma16816(acc[mi][ni], ah, bh[ni]);
#pragma unroll
                for (int ni = 0; ni < 4; ni++) mma16816(acc[mi][ni], al, bh[ni]);
            }
        }
    }

    // epilogue
    const int tg = lane >> 2, tq = lane & 3;
#pragma unroll
    for (int mi = 0; mi < 4; mi++) {
#pragma unroll
        for (int ni = 0; ni < 4; ni++) {
            const float* cc = acc[mi][ni];
            int col = n0 + no + ni * 8 + tq * 2;
            float bx = 0.f, by = 0.f;
            if (BIAS) { bx = bias[col]; by = bias[col + 1]; }
            size_t r0 = (size_t)(m0 + wo + mi * 16 + tg);
            float2 v0 = {cc[0] + bx, cc[1] + by};
            float2 v1 = {cc[2] + bx, cc[3] + by};
            *(float2*)(C + r0 * N + col) = v0;
            *(float2*)(C + (r0 + 8) * N + col) = v1;
        }
    }
}

// ---------------------------------------------------------------------------
// Conversions
// ---------------------------------------------------------------------------
__global__ void convert_A_kernel(const float* __restrict__ X,
                                 __half* __restrict__ Hi,
                                 __half* __restrict__ Lo, size_t total8) {
    size_t t = (size_t)blockIdx.x * blockDim.x + threadIdx.x;
    if (t >= total8) return;
    const float* src = X + t * 8;
    float4 f0 = *(const float4*)src;
    float4 f1 = *(const float4*)(src + 4);
    float v[8] = {f0.x, f0.y, f0.z, f0.w, f1.x, f1.y, f1.z, f1.w};
    union { __half b[8]; uint4 q; } H, L;
#pragma unroll
    for (int i = 0; i < 8; i++) split_f16(v[i], H.b[i], L.b[i]);
    ((uint4*)Hi)[t] = H.q;
    ((uint4*)Lo)[t] = L.q;
}

// W fp32 [1024, Nout] -> transposed fp16 (hi only) [Nout, 1024] via smem tile.
__global__ void convert_W_kernel(const float* __restrict__ W,
                                 __half* __restrict__ Hi, int Nout) {
    __shared__ float tile[32][33];
    const int tx = threadIdx.x & 31, ty = threadIdx.x >> 5;   // 256 threads
    const int n0 = blockIdx.x * 32, k0 = blockIdx.y * 32;
#pragma unroll
    for (int i = 0; i < 4; i++) {
        int k = k0 + ty + i * 8;
        tile[ty + i * 8][tx] = W[(size_t)k * Nout + n0 + tx];
    }
    __syncthreads();
#pragma unroll
    for (int i = 0; i < 4; i++) {
        int n = n0 + ty + i * 8;
        Hi[(size_t)n * DIM + k0 + tx] = __float2half_rn(tile[tx][ty + i * 8]);
    }
}

// ---------------------------------------------------------------------------
// Fused per-token middle stage: RMSNorm(q,k) -> RoPE -> 16x16 scores ->
// softmax -> attn @ v -> fp16 hi/lo row-major (GEMM2 A operand).
// 256 threads per block; 2 tokens per block (128 threads each).
// ---------------------------------------------------------------------------
__global__ __launch_bounds__(256)
void attn_kernel(const float* __restrict__ qkv,
                 const float* __restrict__ fcos, const float* __restrict__ fsin,
                 const float* __restrict__ g_q, const float* __restrict__ g_k,
                 __half* __restrict__ ahi, __half* __restrict__ alo) {
    const int g = threadIdx.x >> 7;        // token slot within block
    const int t = threadIdx.x & 127;
    const int token = blockIdx.x * 2 + g;
    const int n_idx = token & (SEQ - 1);
    const float* row = qkv + (size_t)token * QKVDIM;

    __shared__ float sq[2][NHEAD][HDIM];
    __shared__ float sk[2][NHEAD][HDIM];
    __shared__ float sv[2][NHEAD][HDIM];
    __shared__ float sc[2][HDIM / 2], ss[2][HDIM / 2];
    __shared__ float sscore[2][NHEAD][NHEAD + 1];
    __shared__ __align__(16) float sout[2][DIM];

    for (int i = t; i < DIM / 4; i += 128) {
        ((float4*)&sq[g][0][0])[i] = ((const float4*)row)[i];
        ((float4*)&sk[g][0][0])[i] = ((const float4*)(row + DIM))[i];
        ((float4*)&sv[g][0][0])[i] = ((const float4*)(row + 2 * DIM))[i];
    }
    if (t < HDIM / 2) {
        sc[g][t] = fcos[(size_t)n_idx * (HDIM / 2) + t];
        ss[g][t] = fsin[(size_t)n_idx * (HDIM / 2) + t];
    }
    __syncthreads();

    // RMSNorm + RoPE: 32 tasks (16 q-heads, 16 k-heads), 4 threads each.
    {
        const int task = t >> 2;
        const int l4 = t & 3;
        const int hh = task & (NHEAD - 1);
        float* vec = (task < NHEAD) ? sq[g][hh] : sk[g][hh];
        const float* gg = (task < NHEAD) ? g_q : g_k;

        float ssum = 0.f;
        const int e0 = l4 * 16;
#pragma unroll
        for (int e = 0; e < 16; e++) {
            float v = vec[e0 + e];
            ssum += v * v;
        }
        ssum += __shfl_xor_sync(0xffffffffu, ssum, 1);
        ssum += __shfl_xor_sync(0xffffffffu, ssum, 2);
        float nrm = sqrtf(ssum) * 0.125f;   // ||x|| * d^-0.5, d=64
        float inv = 1.f / (nrm + 1e-6f);

        const int p0 = l4 * 8;
#pragma unroll
        for (int p = 0; p < 8; p++) {
            int pp = p0 + p;
            float re = vec[2 * pp] * inv * gg[2 * pp];
            float im = vec[2 * pp + 1] * inv * gg[2 * pp + 1];
            float cc = sc[g][pp], sn = ss[g][pp];
            vec[2 * pp]     = re * cc - im * sn;
            vec[2 * pp + 1] = re * sn + im * cc;
        }
    }
    __syncthreads();

    for (int e = t; e < NHEAD * NHEAD; e += 128) {
        int i = e >> 4, j = e & 15;
        float a = 0.f;
#pragma unroll
        for (int dd = 0; dd < HDIM; dd++) a += sq[g][i][dd] * sk[g][j][dd];
        sscore[g][i][j] = a * 0.125f;
    }
    __syncthreads();

    if (t < NHEAD) {
        float mx = -1e30f;
#pragma unroll
        for (int j = 0; j < NHEAD; j++) mx = fmaxf(mx, sscore[g][t][j]);
        float sum = 0.f;
#pragma unroll
        for (int j = 0; j < NHEAD; j++) {
            float e2 = expf(sscore[g][t][j] - mx);
            sscore[g][t][j] = e2;
            sum += e2;
        }
        float rr = 1.f / sum;
#pragma unroll
        for (int j = 0; j < NHEAD; j++) sscore[g][t][j] *= rr;
    }
    __syncthreads();

    for (int e = t; e < DIM; e += 128) {
        int i = e >> 6, dd = e & 63;
        float a = 0.f;
#pragma unroll
        for (int j = 0; j < NHEAD; j++) a = fmaf(sscore[g][i][j], sv[g][j][dd], a);
        sout[g][e] = a;
    }
    __syncthreads();

    // fp16 hi/lo split, row-major write (8 consecutive elems per thread).
    {
        const int k0 = t * 8;
        float4 f0 = *(const float4*)&sout[g][k0];
        float4 f1 = *(const float4*)&sout[g][k0 + 4];
        float v[8] = {f0.x, f0.y, f0.z, f0.w, f1.x, f1.y, f1.z, f1.w};
        union { __half b[8]; uint4 q; } H, L;
#pragma unroll
        for (int i = 0; i < 8; i++) split_f16(v[i], H.b[i], L.b[i]);
        size_t base = ((size_t)token * DIM + k0) / 8;
        ((uint4*)ahi)[base] = H.q;
        ((uint4*)alo)[base] = L.q;
    }
}

// ---------------------------------------------------------------------------
extern "C" void kernel_launch(void* const* d_in, const int* in_sizes, int n_in,
                              void* d_out, int out_size) {
    const float* x     = (const float*)d_in[0];
    const float* fcos  = (const float*)d_in[1];
    const float* fsin  = (const float*)d_in[2];
    const float* wqkv  = (const float*)d_in[3];
    const float* gq    = (const float*)d_in[4];
    const float* gk    = (const float*)d_in[5];
    const float* wproj = (const float*)d_in[6];
    const float* bproj = (const float*)d_in[7];
    float* out = (float*)d_out;

    void *p_xhi, *p_xlo, *p_wqhi, *p_wphi, *p_ahi, *p_alo, *p_qkv;
    cudaGetSymbolAddress(&p_xhi,  g_xhi);
    cudaGetSymbolAddress(&p_xlo,  g_xlo);
    cudaGetSymbolAddress(&p_wqhi, g_wqhi);
    cudaGetSymbolAddress(&p_wphi, g_wphi);
    cudaGetSymbolAddress(&p_ahi,  g_ahi);
    cudaGetSymbolAddress(&p_alo,  g_alo);
    cudaGetSymbolAddress(&p_qkv,  g_qkv);

    cudaFuncSetAttribute(mma_gemm<false>, cudaFuncAttributeMaxDynamicSharedMemorySize, GEMM_SMEM);
    cudaFuncSetAttribute(mma_gemm<true>,  cudaFuncAttributeMaxDynamicSharedMemorySize, GEMM_SMEM);

    {
        size_t total8 = (size_t)TOKENS * DIM / 8;
        convert_A_kernel<<<(unsigned)((total8 + 255) / 256), 256>>>(
            x, (__half*)p_xhi, (__half*)p_xlo, total8);
    }
    convert_W_kernel<<<dim3(QKVDIM / 32, DIM / 32), 256>>>(
        wqkv, (__half*)p_wqhi, QKVDIM);
    convert_W_kernel<<<dim3(DIM / 32, DIM / 32), 256>>>(
        wproj, (__half*)p_wphi, DIM);

    // qkv = x @ w_qkv
    mma_gemm<false><<<dim3(QKVDIM / BN, TOKENS / BM), 256, GEMM_SMEM>>>(
        (const __half*)p_xhi, (const __half*)p_xlo,
        (const __half*)p_wqhi, nullptr, (float*)p_qkv, QKVDIM);

    // fused RMSNorm+RoPE+head-mixing attention -> GEMM2 A operand (fp16 hi/lo)
    attn_kernel<<<TOKENS / 2, 256>>>((const float*)p_qkv, fcos, fsin, gq, gk,
                                     (__half*)p_ahi, (__half*)p_alo);

    // out = att @ w_proj + b
    mma_gemm<true><<<dim3(DIM / BN, TOKENS / BM), 256, GEMM_SMEM>>>(
        (const __half*)p_ahi, (const __half*)p_alo,
        (const __half*)p_wphi, bproj, out, DIM);
}

// round 9
// speedup vs baseline: 5.6417x; 1.4312x over previous
#include <cuda_runtime.h>
#include <cuda_bf16.h>
#include <cuda_fp16.h>
#include <stdint.h>
#include <math.h>

// Problem constants: b=4, n=4096 -> T=16384 tokens, dim=1024, heads=16, d=64
#define TOKENS 16384
#define DIM    1024
#define QKVDIM 3072
#define NHEAD  16
#define HDIM   64
#define SEQ    4096

// GEMM tiling (K is always 1024)
#define BM 128
#define BN 128
#define BK 64
#define KCHUNKS (DIM / BK)          // 16
#define STAGES 3
#define ARR_BYTES (BM * BK * 2)     // 16384 per operand array per stage
#define STAGE_BYTES (2 * ARR_BYTES) // 32768 (A, B)
#define GEMM_SMEM (STAGES * STAGE_BYTES)  // 98304

// ---------------------------------------------------------------------------
// Scratch (device globals; kernel_launch is allocation-free)
// ---------------------------------------------------------------------------
__device__ __align__(256) __half g_xh  [(size_t)TOKENS * DIM];
__device__ __align__(256) __half g_wqh [(size_t)QKVDIM * DIM]; // [N,K]
__device__ __align__(256) __half g_wph [(size_t)DIM * DIM];    // [N,K]
__device__ __align__(256) __half g_ah  [(size_t)TOKENS * DIM];
__device__ __align__(256) float  g_qkv [(size_t)TOKENS * QKVDIM];

// ---------------------------------------------------------------------------
// PTX helpers (baseline sm_80+ features only — tcgen05 unavailable on target)
// ---------------------------------------------------------------------------
__device__ __forceinline__ uint32_t s2u(const void* p) {
    uint32_t a;
    asm("{ .reg .u64 t; cvta.to.shared.u64 t, %1; cvt.u32.u64 %0, t; }"
        : "=r"(a) : "l"(p));
    return a;
}

__device__ __forceinline__ void cp_async16(uint32_t dst, const void* gsrc) {
    asm volatile("cp.async.cg.shared.global [%0], [%1], 16;"
                 :: "r"(dst), "l"(__cvta_generic_to_global(gsrc)) : "memory");
}
__device__ __forceinline__ void cp_commit() {
    asm volatile("cp.async.commit_group;" ::: "memory");
}
__device__ __forceinline__ void cp_wait1() {
    asm volatile("cp.async.wait_group 1;" ::: "memory");
}

__device__ __forceinline__ void ldsm_x4(uint32_t& r0, uint32_t& r1,
                                        uint32_t& r2, uint32_t& r3, uint32_t addr) {
    asm volatile("ldmatrix.sync.aligned.m8n8.x4.shared.b16 {%0,%1,%2,%3}, [%4];"
                 : "=r"(r0), "=r"(r1), "=r"(r2), "=r"(r3) : "r"(addr));
}

__device__ __forceinline__ void mma16816(float* c, const uint32_t* a, const uint32_t* b) {
    asm volatile(
        "mma.sync.aligned.m16n8k16.row.col.f32.f16.f16.f32 "
        "{%0,%1,%2,%3}, {%4,%5,%6,%7}, {%8,%9}, {%0,%1,%2,%3};"
        : "+f"(c[0]), "+f"(c[1]), "+f"(c[2]), "+f"(c[3])
        : "r"(a[0]), "r"(a[1]), "r"(a[2]), "r"(a[3]), "r"(b[0]), "r"(b[1]));
}

// Swizzled smem byte offset for a (row, 16B-unit) within a [128][64] f16 tile.
// Row = 128 bytes = 8 units; phys unit = u ^ (row & 7) -> conflict-free for
// both cp.async row writes and ldmatrix 8-row column reads.
__device__ __forceinline__ uint32_t sw_off(int row, int u) {
    return (uint32_t)(row * 128 + (((u ^ (row & 7)) & 7) << 4));
}

// ---------------------------------------------------------------------------
// GEMM: C[M,N] = A @ B^T, A=[M,1024] fp16, B=[N,1024] fp16 (both RN-rounded).
// Single pass, fp32 accumulate.
// grid (N/128, M/128), 256 threads (8 warps, each 64x32). 2 CTAs/SM,
// 3-stage pipeline with prefetch distance 2 (cp.async.wait_group 1).
// ---------------------------------------------------------------------------
template <bool BIAS>
__global__ __launch_bounds__(256, 2)
void mma_gemm(const __half* __restrict__ A, const __half* __restrict__ B,
              const float* __restrict__ bias, float* __restrict__ C, int N) {
    extern __shared__ __align__(256) char smem[];
    const uint32_t sb = s2u(smem);
    const int tid = threadIdx.x;
    const int wid = tid >> 5, lane = tid & 31;
    const int m0 = blockIdx.y * BM;
    const int n0 = blockIdx.x * BN;

    const __half* bases[2] = { A + (size_t)m0 * DIM, B + (size_t)n0 * DIM };

    // --- async stage loader: 2048 x 16B units per stage, 8 per thread ---
    auto load_stage = [&](int s, int c) {
#pragma unroll
        for (int i = 0; i < 8; i++) {
            int u = tid + i * 256;
            int arr = u >> 10;           // 0..1
            int idx = u & 1023;
            int row = idx >> 3;          // 0..127
            int cu  = idx & 7;           // 16B unit within 128B row
            const char* src = (const char*)bases[arr]
                              + (size_t)row * (DIM * 2) + c * (BK * 2) + cu * 16;
            uint32_t dst = sb + s * STAGE_BYTES + arr * ARR_BYTES + sw_off(row, cu);
            cp_async16(dst, src);
        }
    };

    // prologue: stages 0,1 (prefetch distance 2)
    load_stage(0, 0); cp_commit();
    load_stage(1, 1); cp_commit();

    const int wr = wid >> 2, wc = wid & 3;   // 2x4 warp grid
    const int wo = wr * 64, no = wc * 32;

    float acc[4][4][4];
#pragma unroll
    for (int mi = 0; mi < 4; mi++)
#pragma unroll
        for (int ni = 0; ni < 4; ni++)
#pragma unroll
            for (int e = 0; e < 4; e++) acc[mi][ni][e] = 0.f;

    const int la = lane & 15;

    for (int c = 0; c < KCHUNKS; c++) {
        cp_wait1();        // chunk c's group complete (c+1's may be in flight)
        __syncthreads();
        // All warps finished chunk c-1 (they passed this barrier), so buffer
        // (c+2)%3 == (c-1)%3 is free to refill while we compute chunk c.
        const int cn = c + 2;
        if (cn < KCHUNKS) { load_stage(cn % STAGES, cn); cp_commit(); }
        else              { cp_commit(); }   // keep group count in step

        const uint32_t st = sb + (c % STAGES) * STAGE_BYTES;
        const uint32_t sA = st;
        const uint32_t sB = st + ARR_BYTES;

#pragma unroll
        for (int k16 = 0; k16 < 4; k16++) {
            // B fragments for all 4 ni via x4 ldmatrix pairs.
            uint32_t bh[4][2];
            const int brow_lo = (lane >> 4) & 1;         // which ni within pair
            const int bu = k16 * 2 + ((lane >> 3) & 1);  // k-unit
#pragma unroll
            for (int p = 0; p < 2; p++) {
                const int row = no + (p * 2 + brow_lo) * 8 + (lane & 7);
                uint32_t off = sw_off(row, bu);
                ldsm_x4(bh[p*2][0], bh[p*2][1], bh[p*2+1][0], bh[p*2+1][1], sB + off);
            }
            const int au = k16 * 2 + (lane >> 4);
#pragma unroll
            for (int mi = 0; mi < 4; mi++) {
                uint32_t ah[4];
                const int row = wo + mi * 16 + la;
                uint32_t off = sw_off(row, au);
                ldsm_x4(ah[0], ah[1], ah[2], ah[3], sA + off);
#pragma unroll
                for (int ni = 0; ni < 4; ni++) mma16816(acc[mi][ni], ah, bh[ni]);
            }
        }
    }

    // epilogue
    const int tg = lane >> 2, tq = lane & 3;
#pragma unroll
    for (int mi = 0; mi < 4; mi++) {
#pragma unroll
        for (int ni = 0; ni < 4; ni++) {
            const float* cc = acc[mi][ni];
            int col = n0 + no + ni * 8 + tq * 2;
            float bx = 0.f, by = 0.f;
            if (BIAS) { bx = bias[col]; by = bias[col + 1]; }
            size_t r0 = (size_t)(m0 + wo + mi * 16 + tg);
            float2 v0 = {cc[0] + bx, cc[1] + by};
            float2 v1 = {cc[2] + bx, cc[3] + by};
            *(float2*)(C + r0 * N + col) = v0;
            *(float2*)(C + (r0 + 8) * N + col) = v1;
        }
    }
}

// ---------------------------------------------------------------------------
// Conversions
// ---------------------------------------------------------------------------
// fp32 -> fp16 elementwise, 8 per thread.
__global__ void convert_A_kernel(const float* __restrict__ X,
                                 __half* __restrict__ H, size_t total8) {
    size_t t = (size_t)blockIdx.x * blockDim.x + threadIdx.x;
    if (t >= total8) return;
    const float* src = X + t * 8;
    float4 f0 = *(const float4*)src;
    float4 f1 = *(const float4*)(src + 4);
    float v[8] = {f0.x, f0.y, f0.z, f0.w, f1.x, f1.y, f1.z, f1.w};
    union { __half b[8]; uint4 q; } Hh;
#pragma unroll
    for (int i = 0; i < 8; i++) Hh.b[i] = __float2half_rn(v[i]);
    ((uint4*)H)[t] = Hh.q;
}

// W fp32 [1024, Nout] -> transposed fp16 [Nout, 1024] via smem tile.
__global__ void convert_W_kernel(const float* __restrict__ W,
                                 __half* __restrict__ H, int Nout) {
    __shared__ float tile[32][33];
    const int tx = threadIdx.x & 31, ty = threadIdx.x >> 5;   // 256 threads
    const int n0 = blockIdx.x * 32, k0 = blockIdx.y * 32;
#pragma unroll
    for (int i = 0; i < 4; i++) {
        int k = k0 + ty + i * 8;
        tile[ty + i * 8][tx] = W[(size_t)k * Nout + n0 + tx];
    }
    __syncthreads();
#pragma unroll
    for (int i = 0; i < 4; i++) {
        int n = n0 + ty + i * 8;
        H[(size_t)n * DIM + k0 + tx] = __float2half_rn(tile[tx][ty + i * 8]);
    }
}

// ---------------------------------------------------------------------------
// Fused per-token middle stage: RMSNorm(q,k) -> RoPE -> 16x16 scores ->
// softmax -> attn @ v -> fp16 row-major (GEMM2 A operand).
// 256 threads per block; 2 tokens per block (128 threads each).
// ---------------------------------------------------------------------------
__global__ __launch_bounds__(256)
void attn_kernel(const float* __restrict__ qkv,
                 const float* __restrict__ fcos, const float* __restrict__ fsin,
                 const float* __restrict__ g_q, const float* __restrict__ g_k,
                 __half* __restrict__ ah) {
    const int g = threadIdx.x >> 7;        // token slot within block
    const int t = threadIdx.x & 127;
    const int token = blockIdx.x * 2 + g;
    const int n_idx = token & (SEQ - 1);
    const float* row = qkv + (size_t)token * QKVDIM;

    __shared__ float sq[2][NHEAD][HDIM];
    __shared__ float sk[2][NHEAD][HDIM];
    __shared__ float sv[2][NHEAD][HDIM];
    __shared__ float sc[2][HDIM / 2], ss[2][HDIM / 2];
    __shared__ float sscore[2][NHEAD][NHEAD + 1];
    __shared__ __align__(16) float sout[2][DIM];

    for (int i = t; i < DIM / 4; i += 128) {
        ((float4*)&sq[g][0][0])[i] = ((const float4*)row)[i];
        ((float4*)&sk[g][0][0])[i] = ((const float4*)(row + DIM))[i];
        ((float4*)&sv[g][0][0])[i] = ((const float4*)(row + 2 * DIM))[i];
    }
    if (t < HDIM / 2) {
        sc[g][t] = fcos[(size_t)n_idx * (HDIM / 2) + t];
        ss[g][t] = fsin[(size_t)n_idx * (HDIM / 2) + t];
    }
    __syncthreads();

    // RMSNorm + RoPE: 32 tasks (16 q-heads, 16 k-heads), 4 threads each.
    {
        const int task = t >> 2;
        const int l4 = t & 3;
        const int hh = task & (NHEAD - 1);
        float* vec = (task < NHEAD) ? sq[g][hh] : sk[g][hh];
        const float* gg = (task < NHEAD) ? g_q : g_k;

        float ssum = 0.f;
        const int e0 = l4 * 16;
#pragma unroll
        for (int e = 0; e < 16; e++) {
            float v = vec[e0 + e];
            ssum += v * v;
        }
        ssum += __shfl_xor_sync(0xffffffffu, ssum, 1);
        ssum += __shfl_xor_sync(0xffffffffu, ssum, 2);
        float nrm = sqrtf(ssum) * 0.125f;   // ||x|| * d^-0.5, d=64
        float inv = 1.f / (nrm + 1e-6f);

        const int p0 = l4 * 8;
#pragma unroll
        for (int p = 0; p < 8; p++) {
            int pp = p0 + p;
            float re = vec[2 * pp] * inv * gg[2 * pp];
            float im = vec[2 * pp + 1] * inv * gg[2 * pp + 1];
            float cc = sc[g][pp], sn = ss[g][pp];
            vec[2 * pp]     = re * cc - im * sn;
            vec[2 * pp + 1] = re * sn + im * cc;
        }
    }
    __syncthreads();

    for (int e = t; e < NHEAD * NHEAD; e += 128) {
        int i = e >> 4, j = e & 15;
        float a = 0.f;
#pragma unroll
        for (int dd = 0; dd < HDIM; dd++) a += sq[g][i][dd] * sk[g][j][dd];
        sscore[g][i][j] = a * 0.125f;
    }
    __syncthreads();

    if (t < NHEAD) {
        float mx = -1e30f;
#pragma unroll
        for (int j = 0; j < NHEAD; j++) mx = fmaxf(mx, sscore[g][t][j]);
        float sum = 0.f;
#pragma unroll
        for (int j = 0; j < NHEAD; j++) {
            float e2 = expf(sscore[g][t][j] - mx);
            sscore[g][t][j] = e2;
            sum += e2;
        }
        float rr = 1.f / sum;
#pragma unroll
        for (int j = 0; j < NHEAD; j++) sscore[g][t][j] *= rr;
    }
    __syncthreads();

    for (int e = t; e < DIM; e += 128) {
        int i = e >> 6, dd = e & 63;
        float a = 0.f;
#pragma unroll
        for (int j = 0; j < NHEAD; j++) a = fmaf(sscore[g][i][j], sv[g][j][dd], a);
        sout[g][e] = a;
    }
    __syncthreads();

    // fp16 convert, row-major write (8 consecutive elems per thread).
    {
        const int k0 = t * 8;
        float4 f0 = *(const float4*)&sout[g][k0];
        float4 f1 = *(const float4*)&sout[g][k0 + 4];
        float v[8] = {f0.x, f0.y, f0.z, f0.w, f1.x, f1.y, f1.z, f1.w};
        union { __half b[8]; uint4 q; } H;
#pragma unroll
        for (int i = 0; i < 8; i++) H.b[i] = __float2half_rn(v[i]);
        size_t base = ((size_t)token * DIM + k0) / 8;
        ((uint4*)ah)[base] = H.q;
    }
}

// ---------------------------------------------------------------------------
extern "C" void kernel_launch(void* const* d_in, const int* in_sizes, int n_in,
                              void* d_out, int out_size) {
    const float* x     = (const float*)d_in[0];
    const float* fcos  = (const float*)d_in[1];
    const float* fsin  = (const float*)d_in[2];
    const float* wqkv  = (const float*)d_in[3];
    const float* gq    = (const float*)d_in[4];
    const float* gk    = (const float*)d_in[5];
    const float* wproj = (const float*)d_in[6];
    const float* bproj = (const float*)d_in[7];
    float* out = (float*)d_out;

    void *p_xh, *p_wqh, *p_wph, *p_ah, *p_qkv;
    cudaGetSymbolAddress(&p_xh,  g_xh);
    cudaGetSymbolAddress(&p_wqh, g_wqh);
    cudaGetSymbolAddress(&p_wph, g_wph);
    cudaGetSymbolAddress(&p_ah,  g_ah);
    cudaGetSymbolAddress(&p_qkv, g_qkv);

    cudaFuncSetAttribute(mma_gemm<false>, cudaFuncAttributeMaxDynamicSharedMemorySize, GEMM_SMEM);
    cudaFuncSetAttribute(mma_gemm<true>,  cudaFuncAttributeMaxDynamicSharedMemorySize, GEMM_SMEM);

    {
        size_t total8 = (size_t)TOKENS * DIM / 8;
        convert_A_kernel<<<(unsigned)((total8 + 255) / 256), 256>>>(
            x, (__half*)p_xh, total8);
    }
    convert_W_kernel<<<dim3(QKVDIM / 32, DIM / 32), 256>>>(
        wqkv, (__half*)p_wqh, QKVDIM);
    convert_W_kernel<<<dim3(DIM / 32, DIM / 32), 256>>>(
        wproj, (__half*)p_wph, DIM);

    // qkv = x @ w_qkv  (single-pass fp16 MMA, fp32 accum)
    mma_gemm<false><<<dim3(QKVDIM / BN, TOKENS / BM), 256, GEMM_SMEM>>>(
        (const __half*)p_xh, (const __half*)p_wqh, nullptr, (float*)p_qkv, QKVDIM);

    // fused RMSNorm+RoPE+head-mixing attention -> GEMM2 A operand (fp16)
    attn_kernel<<<TOKENS / 2, 256>>>((const float*)p_qkv, fcos, fsin, gq, gk,
                                     (__half*)p_ah);

    // out = att @ w_proj + b
    mma_gemm<true><<<dim3(DIM / BN, TOKENS / BM), 256, GEMM_SMEM>>>(
        (const __half*)p_ah, (const __half*)p_wph, bproj, out, DIM);
}

// round 11
// speedup vs baseline: 5.6989x; 1.0101x over previous
#include <cuda_runtime.h>
#include <cuda_bf16.h>
#include <cuda_fp16.h>
#include <stdint.h>
#include <math.h>

// Problem constants: b=4, n=4096 -> T=16384 tokens, dim=1024, heads=16, d=64
#define TOKENS 16384
#define DIM    1024
#define QKVDIM 3072
#define NHEAD  16
#define HDIM   64
#define SEQ    4096

// GEMM tiling (K is always 1024)
#define BM 128
#define BN 128
#define BK 64
#define KCHUNKS (DIM / BK)          // 16
#define STAGES 3
#define ARR_BYTES (BM * BK * 2)     // 16384 per operand array per stage
#define STAGE_BYTES (2 * ARR_BYTES) // 32768 (A, B)
#define GEMM_SMEM (STAGES * STAGE_BYTES)  // 98304

// ---------------------------------------------------------------------------
// Scratch (device globals; kernel_launch is allocation-free)
// ---------------------------------------------------------------------------
__device__ __align__(256) __half g_xh  [(size_t)TOKENS * DIM];
__device__ __align__(256) __half g_wqh [(size_t)QKVDIM * DIM]; // [N,K]
__device__ __align__(256) __half g_wph [(size_t)DIM * DIM];    // [N,K]
__device__ __align__(256) __half g_ah  [(size_t)TOKENS * DIM];
__device__ __align__(256) __half g_qkv [(size_t)TOKENS * QKVDIM];   // fp16 now

// ---------------------------------------------------------------------------
// PTX helpers (baseline sm_80+ features only — tcgen05 unavailable on target)
// ---------------------------------------------------------------------------
__device__ __forceinline__ uint32_t s2u(const void* p) {
    uint32_t a;
    asm("{ .reg .u64 t; cvta.to.shared.u64 t, %1; cvt.u32.u64 %0, t; }"
        : "=r"(a) : "l"(p));
    return a;
}

__device__ __forceinline__ void cp_async16(uint32_t dst, const void* gsrc) {
    asm volatile("cp.async.cg.shared.global [%0], [%1], 16;"
                 :: "r"(dst), "l"(__cvta_generic_to_global(gsrc)) : "memory");
}
__device__ __forceinline__ void cp_commit() {
    asm volatile("cp.async.commit_group;" ::: "memory");
}
__device__ __forceinline__ void cp_wait1() {
    asm volatile("cp.async.wait_group 1;" ::: "memory");
}

__device__ __forceinline__ void ldsm_x4(uint32_t& r0, uint32_t& r1,
                                        uint32_t& r2, uint32_t& r3, uint32_t addr) {
    asm volatile("ldmatrix.sync.aligned.m8n8.x4.shared.b16 {%0,%1,%2,%3}, [%4];"
                 : "=r"(r0), "=r"(r1), "=r"(r2), "=r"(r3) : "r"(addr));
}

__device__ __forceinline__ void mma16816(float* c, const uint32_t* a, const uint32_t* b) {
    asm volatile(
        "mma.sync.aligned.m16n8k16.row.col.f32.f16.f16.f32 "
        "{%0,%1,%2,%3}, {%4,%5,%6,%7}, {%8,%9}, {%0,%1,%2,%3};"
        : "+f"(c[0]), "+f"(c[1]), "+f"(c[2]), "+f"(c[3])
        : "r"(a[0]), "r"(a[1]), "r"(a[2]), "r"(a[3]), "r"(b[0]), "r"(b[1]));
}

// Swizzled smem byte offset for a (row, 16B-unit) within a [128][64] f16 tile.
__device__ __forceinline__ uint32_t sw_off(int row, int u) {
    return (uint32_t)(row * 128 + (((u ^ (row & 7)) & 7) << 4));
}

// ---------------------------------------------------------------------------
// GEMM: C[M,N] = A @ B^T, A=[M,1024] fp16, B=[N,1024] fp16 (both RN-rounded).
// Single pass, fp32 accumulate. OUTHALF selects fp16 or fp32(+bias) output.
// grid (N/128, M/128), 256 threads (8 warps, each 64x32). 2 CTAs/SM,
// 3-stage pipeline with prefetch distance 2 (cp.async.wait_group 1).
// ---------------------------------------------------------------------------
template <bool BIAS, bool OUTHALF>
__global__ __launch_bounds__(256, 2)
void mma_gemm(const __half* __restrict__ A, const __half* __restrict__ B,
              const float* __restrict__ bias, void* __restrict__ Cout, int N) {
    extern __shared__ __align__(256) char smem[];
    const uint32_t sb = s2u(smem);
    const int tid = threadIdx.x;
    const int wid = tid >> 5, lane = tid & 31;
    const int m0 = blockIdx.y * BM;
    const int n0 = blockIdx.x * BN;

    const __half* bases[2] = { A + (size_t)m0 * DIM, B + (size_t)n0 * DIM };

    // --- async stage loader: 2048 x 16B units per stage, 8 per thread ---
    auto load_stage = [&](int s, int c) {
#pragma unroll
        for (int i = 0; i < 8; i++) {
            int u = tid + i * 256;
            int arr = u >> 10;           // 0..1
            int idx = u & 1023;
            int row = idx >> 3;          // 0..127
            int cu  = idx & 7;           // 16B unit within 128B row
            const char* src = (const char*)bases[arr]
                              + (size_t)row * (DIM * 2) + c * (BK * 2) + cu * 16;
            uint32_t dst = sb + s * STAGE_BYTES + arr * ARR_BYTES + sw_off(row, cu);
            cp_async16(dst, src);
        }
    };

    // prologue: stages 0,1 (prefetch distance 2)
    load_stage(0, 0); cp_commit();
    load_stage(1, 1); cp_commit();

    const int wr = wid >> 2, wc = wid & 3;   // 2x4 warp grid
    const int wo = wr * 64, no = wc * 32;

    float acc[4][4][4];
#pragma unroll
    for (int mi = 0; mi < 4; mi++)
#pragma unroll
        for (int ni = 0; ni < 4; ni++)
#pragma unroll
            for (int e = 0; e < 4; e++) acc[mi][ni][e] = 0.f;

    const int la = lane & 15;

    for (int c = 0; c < KCHUNKS; c++) {
        cp_wait1();        // chunk c's group complete (c+1's may be in flight)
        __syncthreads();
        const int cn = c + 2;
        if (cn < KCHUNKS) { load_stage(cn % STAGES, cn); cp_commit(); }
        else              { cp_commit(); }   // keep group count in step

        const uint32_t st = sb + (c % STAGES) * STAGE_BYTES;
        const uint32_t sA = st;
        const uint32_t sB = st + ARR_BYTES;

#pragma unroll
        for (int k16 = 0; k16 < 4; k16++) {
            uint32_t bh[4][2];
            const int brow_lo = (lane >> 4) & 1;
            const int bu = k16 * 2 + ((lane >> 3) & 1);
#pragma unroll
            for (int p = 0; p < 2; p++) {
                const int row = no + (p * 2 + brow_lo) * 8 + (lane & 7);
                uint32_t off = sw_off(row, bu);
                ldsm_x4(bh[p*2][0], bh[p*2][1], bh[p*2+1][0], bh[p*2+1][1], sB + off);
            }
            const int au = k16 * 2 + (lane >> 4);
#pragma unroll
            for (int mi = 0; mi < 4; mi++) {
                uint32_t ah[4];
                const int row = wo + mi * 16 + la;
                uint32_t off = sw_off(row, au);
                ldsm_x4(ah[0], ah[1], ah[2], ah[3], sA + off);
#pragma unroll
                for (int ni = 0; ni < 4; ni++) mma16816(acc[mi][ni], ah, bh[ni]);
            }
        }
    }

    // epilogue
    const int tg = lane >> 2, tq = lane & 3;
#pragma unroll
    for (int mi = 0; mi < 4; mi++) {
#pragma unroll
        for (int ni = 0; ni < 4; ni++) {
            const float* cc = acc[mi][ni];
            int col = n0 + no + ni * 8 + tq * 2;
            size_t r0 = (size_t)(m0 + wo + mi * 16 + tg);
            if (OUTHALF) {
                __half* C = (__half*)Cout;
                __half2 v0 = __floats2half2_rn(cc[0], cc[1]);
                __half2 v1 = __floats2half2_rn(cc[2], cc[3]);
                *(__half2*)(C + r0 * N + col) = v0;
                *(__half2*)(C + (r0 + 8) * N + col) = v1;
            } else {
                float* C = (float*)Cout;
                float bx = 0.f, by = 0.f;
                if (BIAS) { bx = bias[col]; by = bias[col + 1]; }
                float2 v0 = {cc[0] + bx, cc[1] + by};
                float2 v1 = {cc[2] + bx, cc[3] + by};
                *(float2*)(C + r0 * N + col) = v0;
                *(float2*)(C + (r0 + 8) * N + col) = v1;
            }
        }
    }
}

// ---------------------------------------------------------------------------
// Conversions
// ---------------------------------------------------------------------------
__global__ void convert_A_kernel(const float* __restrict__ X,
                                 __half* __restrict__ H, size_t total8) {
    size_t t = (size_t)blockIdx.x * blockDim.x + threadIdx.x;
    if (t >= total8) return;
    const float* src = X + t * 8;
    float4 f0 = *(const float4*)src;
    float4 f1 = *(const float4*)(src + 4);
    float v[8] = {f0.x, f0.y, f0.z, f0.w, f1.x, f1.y, f1.z, f1.w};
    union { __half b[8]; uint4 q; } Hh;
#pragma unroll
    for (int i = 0; i < 8; i++) Hh.b[i] = __float2half_rn(v[i]);
    ((uint4*)H)[t] = Hh.q;
}

// W fp32 [1024, Nout] -> transposed fp16 [Nout, 1024] via smem tile.
__global__ void convert_W_kernel(const float* __restrict__ W,
                                 __half* __restrict__ H, int Nout) {
    __shared__ float tile[32][33];
    const int tx = threadIdx.x & 31, ty = threadIdx.x >> 5;   // 256 threads
    const int n0 = blockIdx.x * 32, k0 = blockIdx.y * 32;
#pragma unroll
    for (int i = 0; i < 4; i++) {
        int k = k0 + ty + i * 8;
        tile[ty + i * 8][tx] = W[(size_t)k * Nout + n0 + tx];
    }
    __syncthreads();
#pragma unroll
    for (int i = 0; i < 4; i++) {
        int n = n0 + ty + i * 8;
        H[(size_t)n * DIM + k0 + tx] = __float2half_rn(tile[tx][ty + i * 8]);
    }
}

// ---------------------------------------------------------------------------
// Fused per-token middle stage: RMSNorm(q,k) -> RoPE -> 16x16 scores ->
// softmax -> attn @ v -> fp16 row-major (GEMM2 A operand).
// qkv input is fp16 (converted to fp32 in smem). 2 tokens per 256-thr block.
// ---------------------------------------------------------------------------
__global__ __launch_bounds__(256)
void attn_kernel(const __half* __restrict__ qkv,
                 const float* __restrict__ fcos, const float* __restrict__ fsin,
                 const float* __restrict__ g_q, const float* __restrict__ g_k,
                 __half* __restrict__ ah) {
    const int g = threadIdx.x >> 7;        // token slot within block
    const int t = threadIdx.x & 127;
    const int token = blockIdx.x * 2 + g;
    const int n_idx = token & (SEQ - 1);
    const __half* row = qkv + (size_t)token * QKVDIM;

    __shared__ float sq[2][NHEAD][HDIM];
    __shared__ float sk[2][NHEAD][HDIM];
    __shared__ float sv[2][NHEAD][HDIM];
    __shared__ float sc[2][HDIM / 2], ss[2][HDIM / 2];
    __shared__ float sscore[2][NHEAD][NHEAD + 1];
    __shared__ __align__(16) float sout[2][DIM];

    // Each thread loads one 16B unit (8 halves) per array, converts to fp32.
    {
        uint4 uq = ((const uint4*)row)[t];                    // q
        uint4 uk = ((const uint4*)(row + DIM))[t];            // k
        uint4 uv = ((const uint4*)(row + 2 * DIM))[t];        // v
        const __half2* hq = (const __half2*)&uq;
        const __half2* hk = (const __half2*)&uk;
        const __half2* hv = (const __half2*)&uv;
        float* fq = &sq[0][0][0] + g * NHEAD * HDIM + t * 8;
        float* fk = &sk[0][0][0] + g * NHEAD * HDIM + t * 8;
        float* fv = &sv[0][0][0] + g * NHEAD * HDIM + t * 8;
#pragma unroll
        for (int j = 0; j < 4; j++) {
            float2 a = __half22float2(hq[j]); fq[2*j] = a.x; fq[2*j+1] = a.y;
            float2 b = __half22float2(hk[j]); fk[2*j] = b.x; fk[2*j+1] = b.y;
            float2 c = __half22float2(hv[j]); fv[2*j] = c.x; fv[2*j+1] = c.y;
        }
    }
    if (t < HDIM / 2) {
        sc[g][t] = fcos[(size_t)n_idx * (HDIM / 2) + t];
        ss[g][t] = fsin[(size_t)n_idx * (HDIM / 2) + t];
    }
    __syncthreads();

    // RMSNorm + RoPE: 32 tasks (16 q-heads, 16 k-heads), 4 threads each.
    {
        const int task = t >> 2;
        const int l4 = t & 3;
        const int hh = task & (NHEAD - 1);
        float* vec = (task < NHEAD) ? sq[g][hh] : sk[g][hh];
        const float* gg = (task < NHEAD) ? g_q : g_k;

        float ssum = 0.f;
        const int e0 = l4 * 16;
#pragma unroll
        for (int e = 0; e < 16; e++) {
            float v = vec[e0 + e];
            ssum += v * v;
        }
        ssum += __shfl_xor_sync(0xffffffffu, ssum, 1);
        ssum += __shfl_xor_sync(0xffffffffu, ssum, 2);
        float nrm = sqrtf(ssum) * 0.125f;   // ||x|| * d^-0.5, d=64
        float inv = 1.f / (nrm + 1e-6f);

        const int p0 = l4 * 8;
#pragma unroll
        for (int p = 0; p < 8; p++) {
            int pp = p0 + p;
            float re = vec[2 * pp] * inv * gg[2 * pp];
            float im = vec[2 * pp + 1] * inv * gg[2 * pp + 1];
            float cc = sc[g][pp], sn = ss[g][pp];
            vec[2 * pp]     = re * cc - im * sn;
            vec[2 * pp + 1] = re * sn + im * cc;
        }
    }
    __syncthreads();

    for (int e = t; e < NHEAD * NHEAD; e += 128) {
        int i = e >> 4, j = e & 15;
        float a = 0.f;
#pragma unroll
        for (int dd = 0; dd < HDIM; dd++) a += sq[g][i][dd] * sk[g][j][dd];
        sscore[g][i][j] = a * 0.125f;
    }
    __syncthreads();

    if (t < NHEAD) {
        float mx = -1e30f;
#pragma unroll
        for (int j = 0; j < NHEAD; j++) mx = fmaxf(mx, sscore[g][t][j]);
        float sum = 0.f;
#pragma unroll
        for (int j = 0; j < NHEAD; j++) {
            float e2 = expf(sscore[g][t][j] - mx);
            sscore[g][t][j] = e2;
            sum += e2;
        }
        float rr = 1.f / sum;
#pragma unroll
        for (int j = 0; j < NHEAD; j++) sscore[g][t][j] *= rr;
    }
    __syncthreads();

    for (int e = t; e < DIM; e += 128) {
        int i = e >> 6, dd = e & 63;
        float a = 0.f;
#pragma unroll
        for (int j = 0; j < NHEAD; j++) a = fmaf(sscore[g][i][j], sv[g][j][dd], a);
        sout[g][e] = a;
    }
    __syncthreads();

    // fp16 convert, row-major write (8 consecutive elems per thread).
    {
        const int k0 = t * 8;
        float4 f0 = *(const float4*)&sout[g][k0];
        float4 f1 = *(const float4*)&sout[g][k0 + 4];
        float v[8] = {f0.x, f0.y, f0.z, f0.w, f1.x, f1.y, f1.z, f1.w};
        union { __half b[8]; uint4 q; } H;
#pragma unroll
        for (int i = 0; i < 8; i++) H.b[i] = __float2half_rn(v[i]);
        size_t base = ((size_t)token * DIM + k0) / 8;
        ((uint4*)ah)[base] = H.q;
    }
}

// ---------------------------------------------------------------------------
extern "C" void kernel_launch(void* const* d_in, const int* in_sizes, int n_in,
                              void* d_out, int out_size) {
    const float* x     = (const float*)d_in[0];
    const float* fcos  = (const float*)d_in[1];
    const float* fsin  = (const float*)d_in[2];
    const float* wqkv  = (const float*)d_in[3];
    const float* gq    = (const float*)d_in[4];
    const float* gk    = (const float*)d_in[5];
    const float* wproj = (const float*)d_in[6];
    const float* bproj = (const float*)d_in[7];
    float* out = (float*)d_out;

    void *p_xh, *p_wqh, *p_wph, *p_ah, *p_qkv;
    cudaGetSymbolAddress(&p_xh,  g_xh);
    cudaGetSymbolAddress(&p_wqh, g_wqh);
    cudaGetSymbolAddress(&p_wph, g_wph);
    cudaGetSymbolAddress(&p_ah,  g_ah);
    cudaGetSymbolAddress(&p_qkv, g_qkv);

    cudaFuncSetAttribute((const void*)&mma_gemm<false, true>,
                         cudaFuncAttributeMaxDynamicSharedMemorySize, GEMM_SMEM);
    cudaFuncSetAttribute((const void*)&mma_gemm<true, false>,
                         cudaFuncAttributeMaxDynamicSharedMemorySize, GEMM_SMEM);

    {
        size_t total8 = (size_t)TOKENS * DIM / 8;
        convert_A_kernel<<<(unsigned)((total8 + 255) / 256), 256>>>(
            x, (__half*)p_xh, total8);
    }
    convert_W_kernel<<<dim3(QKVDIM / 32, DIM / 32), 256>>>(
        wqkv, (__half*)p_wqh, QKVDIM);
    convert_W_kernel<<<dim3(DIM / 32, DIM / 32), 256>>>(
        wproj, (__half*)p_wph, DIM);

    // qkv = x @ w_qkv  (single-pass fp16 MMA, fp32 accum, fp16 output)
    mma_gemm<false, true><<<dim3(QKVDIM / BN, TOKENS / BM), 256, GEMM_SMEM>>>(
        (const __half*)p_xh, (const __half*)p_wqh, nullptr, p_qkv, QKVDIM);

    // fused RMSNorm+RoPE+head-mixing attention -> GEMM2 A operand (fp16)
    attn_kernel<<<TOKENS / 2, 256>>>((const __half*)p_qkv, fcos, fsin, gq, gk,
                                     (__half*)p_ah);

    // out = att @ w_proj + b  (fp32 output)
    mma_gemm<true, false><<<dim3(DIM / BN, TOKENS / BM), 256, GEMM_SMEM>>>(
        (const __half*)p_ah, (const __half*)p_wph, bproj, out, DIM);
}

// round 12
// speedup vs baseline: 7.8647x; 1.3800x over previous
#include <cuda_runtime.h>
#include <cuda_bf16.h>
#include <cuda_fp16.h>
#include <stdint.h>
#include <math.h>

// Problem constants: b=4, n=4096 -> T=16384 tokens, dim=1024, heads=16, d=64
#define TOKENS 16384
#define DIM    1024
#define QKVDIM 3072
#define NHEAD  16
#define HDIM   64
#define SEQ    4096

// GEMM tiling (K is always 1024)
#define BM 128
#define BN 128
#define BK 64
#define KCHUNKS (DIM / BK)          // 16
#define STAGES 3
#define ARR_BYTES (BM * BK * 2)     // 16384 per operand array per stage
#define STAGE_BYTES (2 * ARR_BYTES) // 32768 (A, B)
#define GEMM_SMEM (STAGES * STAGE_BYTES)  // 98304

// ---------------------------------------------------------------------------
// Scratch (device globals; kernel_launch is allocation-free)
// ---------------------------------------------------------------------------
__device__ __align__(256) __half g_xh  [(size_t)TOKENS * DIM];
__device__ __align__(256) __half g_wqh [(size_t)QKVDIM * DIM]; // [N,K]
__device__ __align__(256) __half g_wph [(size_t)DIM * DIM];    // [N,K]
__device__ __align__(256) __half g_ah  [(size_t)TOKENS * DIM];
__device__ __align__(256) float  g_qkv [(size_t)TOKENS * QKVDIM];  // fp32 (margin)

// ---------------------------------------------------------------------------
// PTX helpers (baseline sm_80+ features only — tcgen05 unavailable on target)
// ---------------------------------------------------------------------------
__device__ __forceinline__ uint32_t s2u(const void* p) {
    uint32_t a;
    asm("{ .reg .u64 t; cvta.to.shared.u64 t, %1; cvt.u32.u64 %0, t; }"
        : "=r"(a) : "l"(p));
    return a;
}

__device__ __forceinline__ void cp_async16(uint32_t dst, const void* gsrc) {
    asm volatile("cp.async.cg.shared.global [%0], [%1], 16;"
                 :: "r"(dst), "l"(__cvta_generic_to_global(gsrc)) : "memory");
}
__device__ __forceinline__ void cp_commit() {
    asm volatile("cp.async.commit_group;" ::: "memory");
}
__device__ __forceinline__ void cp_wait1() {
    asm volatile("cp.async.wait_group 1;" ::: "memory");
}

__device__ __forceinline__ void ldsm_x4(uint32_t& r0, uint32_t& r1,
                                        uint32_t& r2, uint32_t& r3, uint32_t addr) {
    asm volatile("ldmatrix.sync.aligned.m8n8.x4.shared.b16 {%0,%1,%2,%3}, [%4];"
                 : "=r"(r0), "=r"(r1), "=r"(r2), "=r"(r3) : "r"(addr));
}
__device__ __forceinline__ void ldsm_x4_t(uint32_t& r0, uint32_t& r1,
                                          uint32_t& r2, uint32_t& r3, uint32_t addr) {
    asm volatile("ldmatrix.sync.aligned.m8n8.x4.trans.shared.b16 {%0,%1,%2,%3}, [%4];"
                 : "=r"(r0), "=r"(r1), "=r"(r2), "=r"(r3) : "r"(addr));
}

__device__ __forceinline__ void mma16816(float* c, const uint32_t* a, const uint32_t* b) {
    asm volatile(
        "mma.sync.aligned.m16n8k16.row.col.f32.f16.f16.f32 "
        "{%0,%1,%2,%3}, {%4,%5,%6,%7}, {%8,%9}, {%0,%1,%2,%3};"
        : "+f"(c[0]), "+f"(c[1]), "+f"(c[2]), "+f"(c[3])
        : "r"(a[0]), "r"(a[1]), "r"(a[2]), "r"(a[3]), "r"(b[0]), "r"(b[1]));
}

// Swizzled smem byte offset for a (row, 16B-unit) within a [rows][64] f16 tile.
__device__ __forceinline__ uint32_t sw_off(int row, int u) {
    return (uint32_t)(row * 128 + (((u ^ (row & 7)) & 7) << 4));
}

// ---------------------------------------------------------------------------
// GEMM: C[M,N] = A @ B^T, fp16 operands, fp32 accumulate.
// OUTHALF selects fp16 or fp32(+bias) output.
// grid (N/128, M/128), 256 threads (8 warps, each 64x32). 2 CTAs/SM,
// 3-stage pipeline with prefetch distance 2 (cp.async.wait_group 1).
// ---------------------------------------------------------------------------
template <bool BIAS, bool OUTHALF>
__global__ __launch_bounds__(256, 2)
void mma_gemm(const __half* __restrict__ A, const __half* __restrict__ B,
              const float* __restrict__ bias, void* __restrict__ Cout, int N) {
    extern __shared__ __align__(256) char smem[];
    const uint32_t sb = s2u(smem);
    const int tid = threadIdx.x;
    const int wid = tid >> 5, lane = tid & 31;
    const int m0 = blockIdx.y * BM;
    const int n0 = blockIdx.x * BN;

    const __half* bases[2] = { A + (size_t)m0 * DIM, B + (size_t)n0 * DIM };

    auto load_stage = [&](int s, int c) {
#pragma unroll
        for (int i = 0; i < 8; i++) {
            int u = tid + i * 256;
            int arr = u >> 10;
            int idx = u & 1023;
            int row = idx >> 3;
            int cu  = idx & 7;
            const char* src = (const char*)bases[arr]
                              + (size_t)row * (DIM * 2) + c * (BK * 2) + cu * 16;
            uint32_t dst = sb + s * STAGE_BYTES + arr * ARR_BYTES + sw_off(row, cu);
            cp_async16(dst, src);
        }
    };

    load_stage(0, 0); cp_commit();
    load_stage(1, 1); cp_commit();

    const int wr = wid >> 2, wc = wid & 3;
    const int wo = wr * 64, no = wc * 32;

    float acc[4][4][4];
#pragma unroll
    for (int mi = 0; mi < 4; mi++)
#pragma unroll
        for (int ni = 0; ni < 4; ni++)
#pragma unroll
            for (int e = 0; e < 4; e++) acc[mi][ni][e] = 0.f;

    const int la = lane & 15;

    for (int c = 0; c < KCHUNKS; c++) {
        cp_wait1();
        __syncthreads();
        const int cn = c + 2;
        if (cn < KCHUNKS) { load_stage(cn % STAGES, cn); cp_commit(); }
        else              { cp_commit(); }

        const uint32_t st = sb + (c % STAGES) * STAGE_BYTES;
        const uint32_t sA = st;
        const uint32_t sB = st + ARR_BYTES;

#pragma unroll
        for (int k16 = 0; k16 < 4; k16++) {
            uint32_t bh[4][2];
            const int brow_lo = (lane >> 4) & 1;
            const int bu = k16 * 2 + ((lane >> 3) & 1);
#pragma unroll
            for (int p = 0; p < 2; p++) {
                const int row = no + (p * 2 + brow_lo) * 8 + (lane & 7);
                uint32_t off = sw_off(row, bu);
                ldsm_x4(bh[p*2][0], bh[p*2][1], bh[p*2+1][0], bh[p*2+1][1], sB + off);
            }
            const int au = k16 * 2 + (lane >> 4);
#pragma unroll
            for (int mi = 0; mi < 4; mi++) {
                uint32_t ah[4];
                const int row = wo + mi * 16 + la;
                uint32_t off = sw_off(row, au);
                ldsm_x4(ah[0], ah[1], ah[2], ah[3], sA + off);
#pragma unroll
                for (int ni = 0; ni < 4; ni++) mma16816(acc[mi][ni], ah, bh[ni]);
            }
        }
    }

    const int tg = lane >> 2, tq = lane & 3;
#pragma unroll
    for (int mi = 0; mi < 4; mi++) {
#pragma unroll
        for (int ni = 0; ni < 4; ni++) {
            const float* cc = acc[mi][ni];
            int col = n0 + no + ni * 8 + tq * 2;
            size_t r0 = (size_t)(m0 + wo + mi * 16 + tg);
            if (OUTHALF) {
                __half* C = (__half*)Cout;
                *(__half2*)(C + r0 * N + col) = __floats2half2_rn(cc[0], cc[1]);
                *(__half2*)(C + (r0 + 8) * N + col) = __floats2half2_rn(cc[2], cc[3]);
            } else {
                float* C = (float*)Cout;
                float bx = 0.f, by = 0.f;
                if (BIAS) { bx = bias[col]; by = bias[col + 1]; }
                float2 v0 = {cc[0] + bx, cc[1] + by};
                float2 v1 = {cc[2] + bx, cc[3] + by};
                *(float2*)(C + r0 * N + col) = v0;
                *(float2*)(C + (r0 + 8) * N + col) = v1;
            }
        }
    }
}

// ---------------------------------------------------------------------------
// Conversions
// ---------------------------------------------------------------------------
__global__ void convert_A_kernel(const float* __restrict__ X,
                                 __half* __restrict__ H, size_t total8) {
    size_t t = (size_t)blockIdx.x * blockDim.x + threadIdx.x;
    if (t >= total8) return;
    const float* src = X + t * 8;
    float4 f0 = *(const float4*)src;
    float4 f1 = *(const float4*)(src + 4);
    float v[8] = {f0.x, f0.y, f0.z, f0.w, f1.x, f1.y, f1.z, f1.w};
    union { __half b[8]; uint4 q; } Hh;
#pragma unroll
    for (int i = 0; i < 8; i++) Hh.b[i] = __float2half_rn(v[i]);
    ((uint4*)H)[t] = Hh.q;
}

__global__ void convert_W_kernel(const float* __restrict__ W,
                                 __half* __restrict__ H, int Nout) {
    __shared__ float tile[32][33];
    const int tx = threadIdx.x & 31, ty = threadIdx.x >> 5;
    const int n0 = blockIdx.x * 32, k0 = blockIdx.y * 32;
#pragma unroll
    for (int i = 0; i < 4; i++) {
        int k = k0 + ty + i * 8;
        tile[ty + i * 8][tx] = W[(size_t)k * Nout + n0 + tx];
    }
    __syncthreads();
#pragma unroll
    for (int i = 0; i < 4; i++) {
        int n = n0 + ty + i * 8;
        H[(size_t)n * DIM + k0 + tx] = __float2half_rn(tile[tx][ty + i * 8]);
    }
}

// ---------------------------------------------------------------------------
// Fused middle stage, warp-per-token, MMA-based:
// RMSNorm+RoPE (lane-per-head, fp32 regs) -> S=QK^T via mma (m16n16k64) ->
// softmax on fragments (4-lane shfl) -> O=PV via mma (trans-ldmatrix V) ->
// fp16 out to ah. 8 warps/block = 8 tokens; no block-wide barriers.
// ---------------------------------------------------------------------------
__global__ __launch_bounds__(256)
void attn_kernel(const float* __restrict__ qkv,
                 const float* __restrict__ fcos, const float* __restrict__ fsin,
                 const float* __restrict__ g_q, const float* __restrict__ g_k,
                 __half* __restrict__ ah) {
    __shared__ __align__(16) __half sQ[8][NHEAD * HDIM];   // 2KB per warp
    __shared__ __align__(16) __half sK[8][NHEAD * HDIM];
    __shared__ __align__(16) __half sV[8][NHEAD * HDIM];

    const int w = threadIdx.x >> 5;
    const int lane = threadIdx.x & 31;
    const int token = blockIdx.x * 8 + w;
    const int n_idx = token & (SEQ - 1);
    const float* base = qkv + (size_t)token * QKVDIM;

    const uint32_t qb = s2u(&sQ[w][0]);
    const uint32_t kb = s2u(&sK[w][0]);
    const uint32_t vb = s2u(&sV[w][0]);

    // ---- Phase 1a: q (lanes 0-15) / k (lanes 16-31): one head per lane ----
    {
        const int hh = lane & 15;
        const float* src = base + (lane < 16 ? 0 : DIM) + hh * HDIM;
        float vr[64];
#pragma unroll
        for (int i = 0; i < 16; i++) ((float4*)vr)[i] = ((const float4*)src)[i];
        float ssum = 0.f;
#pragma unroll
        for (int e = 0; e < 64; e++) ssum += vr[e] * vr[e];
        float inv = 1.f / (sqrtf(ssum) * 0.125f + 1e-6f);   // ||x||*d^-0.5, d=64
        const float* gg = (lane < 16) ? g_q : g_k;

        union { __half2 h[4]; uint4 u; } pk[8];
#pragma unroll
        for (int p = 0; p < 32; p++) {
            float cc = fcos[n_idx * 32 + p];
            float sn = fsin[n_idx * 32 + p];
            float re = vr[2 * p] * inv * gg[2 * p];
            float im = vr[2 * p + 1] * inv * gg[2 * p + 1];
            pk[p >> 2].h[p & 3] = __floats2half2_rn(re * cc - im * sn,
                                                    re * sn + im * cc);
        }
        char* dst = (char*)((lane < 16) ? &sQ[w][0] : &sK[w][0]);
#pragma unroll
        for (int u = 0; u < 8; u++)
            *(uint4*)(dst + sw_off(hh, u)) = pk[u].u;
    }
    // ---- Phase 1b: v -> fp16 swizzled smem (each lane: half a row) ----
    {
        const float* vsrc = base + 2 * DIM + lane * 32;
        float4 vv[8];
#pragma unroll
        for (int i = 0; i < 8; i++) vv[i] = ((const float4*)vsrc)[i];
        const int row = lane >> 1, ub = (lane & 1) * 4;
        char* dst = (char*)&sV[w][0];
#pragma unroll
        for (int u2 = 0; u2 < 4; u2++) {
            union { __half2 h[4]; uint4 u; } pk;
            pk.h[0] = __floats2half2_rn(vv[2*u2].x, vv[2*u2].y);
            pk.h[1] = __floats2half2_rn(vv[2*u2].z, vv[2*u2].w);
            pk.h[2] = __floats2half2_rn(vv[2*u2+1].x, vv[2*u2+1].y);
            pk.h[3] = __floats2half2_rn(vv[2*u2+1].z, vv[2*u2+1].w);
            *(uint4*)(dst + sw_off(row, ub + u2)) = pk.u;
        }
    }
    __syncwarp();

    // ---- Phase 2: S = Q K^T (m16n16k64 => 2 n-tiles x 4 k16) ----
    float accS[2][4] = {{0.f,0.f,0.f,0.f},{0.f,0.f,0.f,0.f}};
#pragma unroll
    for (int kk = 0; kk < 4; kk++) {
        uint32_t a[4];
        {
            const int row = lane & 15;
            const int au = kk * 2 + (lane >> 4);
            ldsm_x4(a[0], a[1], a[2], a[3], qb + sw_off(row, au));
        }
        uint32_t b[4];
        {
            const int row = ((lane >> 4) & 1) * 8 + (lane & 7);
            const int bu = kk * 2 + ((lane >> 3) & 1);
            ldsm_x4(b[0], b[1], b[2], b[3], kb + sw_off(row, bu));
        }
        mma16816(accS[0], a, b);
        mma16816(accS[1], a, b + 2);
    }

    // ---- Phase 3: softmax over 16 cols (rows r=lane/4 and r+8) ----
    // lane holds: row r: accS[t][0..1]; row r+8: accS[t][2..3] (t = col tile)
    float m0 = fmaxf(fmaxf(accS[0][0], accS[0][1]), fmaxf(accS[1][0], accS[1][1]));
    float m1 = fmaxf(fmaxf(accS[0][2], accS[0][3]), fmaxf(accS[1][2], accS[1][3]));
    m0 = fmaxf(m0, __shfl_xor_sync(0xffffffffu, m0, 1));
    m0 = fmaxf(m0, __shfl_xor_sync(0xffffffffu, m0, 2));
    m1 = fmaxf(m1, __shfl_xor_sync(0xffffffffu, m1, 1));
    m1 = fmaxf(m1, __shfl_xor_sync(0xffffffffu, m1, 2));
    float e00 = __expf(0.125f * (accS[0][0] - m0));
    float e01 = __expf(0.125f * (accS[0][1] - m0));
    float e10 = __expf(0.125f * (accS[1][0] - m0));
    float e11 = __expf(0.125f * (accS[1][1] - m0));
    float f00 = __expf(0.125f * (accS[0][2] - m1));
    float f01 = __expf(0.125f * (accS[0][3] - m1));
    float f10 = __expf(0.125f * (accS[1][2] - m1));
    float f11 = __expf(0.125f * (accS[1][3] - m1));
    float s0 = e00 + e01 + e10 + e11;
    float s1 = f00 + f01 + f10 + f11;
    s0 += __shfl_xor_sync(0xffffffffu, s0, 1);
    s0 += __shfl_xor_sync(0xffffffffu, s0, 2);
    s1 += __shfl_xor_sync(0xffffffffu, s1, 1);
    s1 += __shfl_xor_sync(0xffffffffu, s1, 2);
    float r0i = 1.f / s0, r1i = 1.f / s1;

    // ---- Phase 4: P fragments (A m16k16 layout == accum layout pairing) ----
    uint32_t aP[4];
    {
        __half2 h;
        h = __floats2half2_rn(e00 * r0i, e01 * r0i); aP[0] = *(uint32_t*)&h;
        h = __floats2half2_rn(f00 * r1i, f01 * r1i); aP[1] = *(uint32_t*)&h;
        h = __floats2half2_rn(e10 * r0i, e11 * r0i); aP[2] = *(uint32_t*)&h;
        h = __floats2half2_rn(f10 * r1i, f11 * r1i); aP[3] = *(uint32_t*)&h;
    }

    // ---- Phase 5: O = P @ V (m16n64k16 => 8 n-tiles, trans-ldmatrix V) ----
    float accO[8][4];
#pragma unroll
    for (int t = 0; t < 8; t++)
#pragma unroll
        for (int e = 0; e < 4; e++) accO[t][e] = 0.f;
#pragma unroll
    for (int dt2 = 0; dt2 < 4; dt2++) {
        uint32_t b[4];
        const int grp = lane >> 3;
        const int krow = (grp & 1) * 8 + (lane & 7);
        const int dt = dt2 * 2 + (grp >> 1);
        ldsm_x4_t(b[0], b[1], b[2], b[3], vb + sw_off(krow, dt));
        mma16816(accO[2 * dt2], aP, b);
        mma16816(accO[2 * dt2 + 1], aP, b + 2);
    }

    // ---- Phase 6: write O to ah (fp16, row = head, col = d) ----
    {
        __half* orow = ah + (size_t)token * DIM;
        const int rr = lane >> 2, cc0 = 2 * (lane & 3);
#pragma unroll
        for (int t = 0; t < 8; t++) {
            *(__half2*)(orow + rr * HDIM + t * 8 + cc0) =
                __floats2half2_rn(accO[t][0], accO[t][1]);
            *(__half2*)(orow + (rr + 8) * HDIM + t * 8 + cc0) =
                __floats2half2_rn(accO[t][2], accO[t][3]);
        }
    }
}

// ---------------------------------------------------------------------------
extern "C" void kernel_launch(void* const* d_in, const int* in_sizes, int n_in,
                              void* d_out, int out_size) {
    const float* x     = (const float*)d_in[0];
    const float* fcos  = (const float*)d_in[1];
    const float* fsin  = (const float*)d_in[2];
    const float* wqkv  = (const float*)d_in[3];
    const float* gq    = (const float*)d_in[4];
    const float* gk    = (const float*)d_in[5];
    const float* wproj = (const float*)d_in[6];
    const float* bproj = (const float*)d_in[7];
    float* out = (float*)d_out;

    void *p_xh, *p_wqh, *p_wph, *p_ah, *p_qkv;
    cudaGetSymbolAddress(&p_xh,  g_xh);
    cudaGetSymbolAddress(&p_wqh, g_wqh);
    cudaGetSymbolAddress(&p_wph, g_wph);
    cudaGetSymbolAddress(&p_ah,  g_ah);
    cudaGetSymbolAddress(&p_qkv, g_qkv);

    cudaFuncSetAttribute((const void*)&mma_gemm<false, false>,
                         cudaFuncAttributeMaxDynamicSharedMemorySize, GEMM_SMEM);
    cudaFuncSetAttribute((const void*)&mma_gemm<true, false>,
                         cudaFuncAttributeMaxDynamicSharedMemorySize, GEMM_SMEM);

    {
        size_t total8 = (size_t)TOKENS * DIM / 8;
        convert_A_kernel<<<(unsigned)((total8 + 255) / 256), 256>>>(
            x, (__half*)p_xh, total8);
    }
    convert_W_kernel<<<dim3(QKVDIM / 32, DIM / 32), 256>>>(
        wqkv, (__half*)p_wqh, QKVDIM);
    convert_W_kernel<<<dim3(DIM / 32, DIM / 32), 256>>>(
        wproj, (__half*)p_wph, DIM);

    // qkv = x @ w_qkv  (single-pass fp16 MMA, fp32 accum, fp32 output)
    mma_gemm<false, false><<<dim3(QKVDIM / BN, TOKENS / BM), 256, GEMM_SMEM>>>(
        (const __half*)p_xh, (const __half*)p_wqh, nullptr, p_qkv, QKVDIM);

    // fused RMSNorm+RoPE+head-mixing attention (MMA) -> ah fp16
    attn_kernel<<<TOKENS / 8, 256>>>((const float*)p_qkv, fcos, fsin, gq, gk,
                                     (__half*)p_ah);

    // out = att @ w_proj + b  (fp32 output)
    mma_gemm<true, false><<<dim3(DIM / BN, TOKENS / BM), 256, GEMM_SMEM>>>(
        (const __half*)p_ah, (const __half*)p_wph, bproj, out, DIM);
}

// round 13
// speedup vs baseline: 7.8848x; 1.0026x over previous
#include <cuda_runtime.h>
#include <cuda_bf16.h>
#include <cuda_fp16.h>
#include <stdint.h>
#include <math.h>

// Problem constants: b=4, n=4096 -> T=16384 tokens, dim=1024, heads=16, d=64
#define TOKENS 16384
#define DIM    1024
#define QKVDIM 3072
#define NHEAD  16
#define HDIM   64
#define SEQ    4096

// GEMM tiling (K is always 1024)
#define BM 128
#define BN 128
#define BK 64
#define KCHUNKS (DIM / BK)          // 16
#define STAGES 3
#define ARR_BYTES (BM * BK * 2)     // 16384 per operand array per stage
#define STAGE_BYTES (2 * ARR_BYTES) // 32768 (A, B)
#define GEMM_SMEM (STAGES * STAGE_BYTES)  // 98304

// ---------------------------------------------------------------------------
// Scratch (device globals; kernel_launch is allocation-free)
// ---------------------------------------------------------------------------
__device__ __align__(256) __half g_xh  [(size_t)TOKENS * DIM];
__device__ __align__(256) __half g_wqh [(size_t)QKVDIM * DIM]; // [N,K]
__device__ __align__(256) __half g_wph [(size_t)DIM * DIM];    // [N,K]
__device__ __align__(256) __half g_ah  [(size_t)TOKENS * DIM];
__device__ __align__(256) float  g_qkv [(size_t)TOKENS * QKVDIM];

// ---------------------------------------------------------------------------
// PTX helpers (baseline sm_80+ features only — tcgen05 unavailable on target)
// ---------------------------------------------------------------------------
__device__ __forceinline__ uint32_t s2u(const void* p) {
    uint32_t a;
    asm("{ .reg .u64 t; cvta.to.shared.u64 t, %1; cvt.u32.u64 %0, t; }"
        : "=r"(a) : "l"(p));
    return a;
}

__device__ __forceinline__ void cp_async16(uint32_t dst, const void* gsrc) {
    asm volatile("cp.async.cg.shared.global [%0], [%1], 16;"
                 :: "r"(dst), "l"(__cvta_generic_to_global(gsrc)) : "memory");
}
__device__ __forceinline__ void cp_commit() {
    asm volatile("cp.async.commit_group;" ::: "memory");
}
__device__ __forceinline__ void cp_wait1() {
    asm volatile("cp.async.wait_group 1;" ::: "memory");
}

__device__ __forceinline__ void ldsm_x4(uint32_t& r0, uint32_t& r1,
                                        uint32_t& r2, uint32_t& r3, uint32_t addr) {
    asm volatile("ldmatrix.sync.aligned.m8n8.x4.shared.b16 {%0,%1,%2,%3}, [%4];"
                 : "=r"(r0), "=r"(r1), "=r"(r2), "=r"(r3) : "r"(addr));
}
__device__ __forceinline__ void ldsm_x4_t(uint32_t& r0, uint32_t& r1,
                                          uint32_t& r2, uint32_t& r3, uint32_t addr) {
    asm volatile("ldmatrix.sync.aligned.m8n8.x4.trans.shared.b16 {%0,%1,%2,%3}, [%4];"
                 : "=r"(r0), "=r"(r1), "=r"(r2), "=r"(r3) : "r"(addr));
}

__device__ __forceinline__ void mma16816(float* c, const uint32_t* a, const uint32_t* b) {
    asm volatile(
        "mma.sync.aligned.m16n8k16.row.col.f32.f16.f16.f32 "
        "{%0,%1,%2,%3}, {%4,%5,%6,%7}, {%8,%9}, {%0,%1,%2,%3};"
        : "+f"(c[0]), "+f"(c[1]), "+f"(c[2]), "+f"(c[3])
        : "r"(a[0]), "r"(a[1]), "r"(a[2]), "r"(a[3]), "r"(b[0]), "r"(b[1]));
}

// Swizzled smem byte offset for a (row, 16B-unit) within a [rows][64] f16 tile.
__device__ __forceinline__ uint32_t sw_off(int row, int u) {
    return (uint32_t)(row * 128 + (((u ^ (row & 7)) & 7) << 4));
}

// ---------------------------------------------------------------------------
// GEMM: C[M,N] = A @ B^T, fp16 operands, fp32 accumulate.
// OUTHALF selects fp16 or fp32(+bias) output.
// grid (N/128, M/128), 128 threads = 4 warps, each warp 64x64.
// 2 CTAs/SM, 3-stage pipeline, prefetch distance 2 (cp.async.wait_group 1).
// ---------------------------------------------------------------------------
template <bool BIAS, bool OUTHALF>
__global__ __launch_bounds__(128, 2)
void mma_gemm(const __half* __restrict__ A, const __half* __restrict__ B,
              const float* __restrict__ bias, void* __restrict__ Cout, int N) {
    extern __shared__ __align__(256) char smem[];
    const uint32_t sb = s2u(smem);
    const int tid = threadIdx.x;
    const int wid = tid >> 5, lane = tid & 31;
    const int m0 = blockIdx.y * BM;
    const int n0 = blockIdx.x * BN;

    const __half* bases[2] = { A + (size_t)m0 * DIM, B + (size_t)n0 * DIM };

    // --- async stage loader: 2048 x 16B units per stage, 16 per thread ---
    auto load_stage = [&](int s, int c) {
#pragma unroll
        for (int i = 0; i < 16; i++) {
            int u = tid + i * 128;
            int arr = u >> 10;           // 0..1
            int idx = u & 1023;
            int row = idx >> 3;          // 0..127
            int cu  = idx & 7;           // 16B unit within 128B row
            const char* src = (const char*)bases[arr]
                              + (size_t)row * (DIM * 2) + c * (BK * 2) + cu * 16;
            uint32_t dst = sb + s * STAGE_BYTES + arr * ARR_BYTES + sw_off(row, cu);
            cp_async16(dst, src);
        }
    };

    load_stage(0, 0); cp_commit();
    load_stage(1, 1); cp_commit();

    const int wr = wid >> 1, wc = wid & 1;   // 2x2 warp grid
    const int wo = wr * 64, no = wc * 64;

    float acc[4][8][4];
#pragma unroll
    for (int mi = 0; mi < 4; mi++)
#pragma unroll
        for (int ni = 0; ni < 8; ni++)
#pragma unroll
            for (int e = 0; e < 4; e++) acc[mi][ni][e] = 0.f;

    const int la = lane & 15;

    for (int c = 0; c < KCHUNKS; c++) {
        cp_wait1();
        __syncthreads();
        const int cn = c + 2;
        if (cn < KCHUNKS) { load_stage(cn % STAGES, cn); cp_commit(); }
        else              { cp_commit(); }   // keep group count in step

        const uint32_t st = sb + (c % STAGES) * STAGE_BYTES;
        const uint32_t sA = st;
        const uint32_t sB = st + ARR_BYTES;

#pragma unroll
        for (int k16 = 0; k16 < 4; k16++) {
            // B fragments for all 8 ni via x4 ldmatrix pairs.
            uint32_t bh[8][2];
            const int brow_lo = (lane >> 4) & 1;         // which ni within pair
            const int bu = k16 * 2 + ((lane >> 3) & 1);  // k-unit
#pragma unroll
            for (int p = 0; p < 4; p++) {
                const int row = no + (p * 2 + brow_lo) * 8 + (lane & 7);
                uint32_t off = sw_off(row, bu);
                ldsm_x4(bh[p*2][0], bh[p*2][1], bh[p*2+1][0], bh[p*2+1][1], sB + off);
            }
            const int au = k16 * 2 + (lane >> 4);
#pragma unroll
            for (int mi = 0; mi < 4; mi++) {
                uint32_t ah[4];
                const int row = wo + mi * 16 + la;
                uint32_t off = sw_off(row, au);
                ldsm_x4(ah[0], ah[1], ah[2], ah[3], sA + off);
#pragma unroll
                for (int ni = 0; ni < 8; ni++) mma16816(acc[mi][ni], ah, bh[ni]);
            }
        }
    }

    // epilogue
    const int tg = lane >> 2, tq = lane & 3;
#pragma unroll
    for (int mi = 0; mi < 4; mi++) {
#pragma unroll
        for (int ni = 0; ni < 8; ni++) {
            const float* cc = acc[mi][ni];
            int col = n0 + no + ni * 8 + tq * 2;
            size_t r0 = (size_t)(m0 + wo + mi * 16 + tg);
            if (OUTHALF) {
                __half* C = (__half*)Cout;
                *(__half2*)(C + r0 * N + col) = __floats2half2_rn(cc[0], cc[1]);
                *(__half2*)(C + (r0 + 8) * N + col) = __floats2half2_rn(cc[2], cc[3]);
            } else {
                float* C = (float*)Cout;
                float bx = 0.f, by = 0.f;
                if (BIAS) { bx = bias[col]; by = bias[col + 1]; }
                float2 v0 = {cc[0] + bx, cc[1] + by};
                float2 v1 = {cc[2] + bx, cc[3] + by};
                *(float2*)(C + r0 * N + col) = v0;
                *(float2*)(C + (r0 + 8) * N + col) = v1;
            }
        }
    }
}

// ---------------------------------------------------------------------------
// Conversions
// ---------------------------------------------------------------------------
__global__ void convert_A_kernel(const float* __restrict__ X,
                                 __half* __restrict__ H, size_t total8) {
    size_t t = (size_t)blockIdx.x * blockDim.x + threadIdx.x;
    if (t >= total8) return;
    const float* src = X + t * 8;
    float4 f0 = *(const float4*)src;
    float4 f1 = *(const float4*)(src + 4);
    float v[8] = {f0.x, f0.y, f0.z, f0.w, f1.x, f1.y, f1.z, f1.w};
    union { __half b[8]; uint4 q; } Hh;
#pragma unroll
    for (int i = 0; i < 8; i++) Hh.b[i] = __float2half_rn(v[i]);
    ((uint4*)H)[t] = Hh.q;
}

__global__ void convert_W_kernel(const float* __restrict__ W,
                                 __half* __restrict__ H, int Nout) {
    __shared__ float tile[32][33];
    const int tx = threadIdx.x & 31, ty = threadIdx.x >> 5;
    const int n0 = blockIdx.x * 32, k0 = blockIdx.y * 32;
#pragma unroll
    for (int i = 0; i < 4; i++) {
        int k = k0 + ty + i * 8;
        tile[ty + i * 8][tx] = W[(size_t)k * Nout + n0 + tx];
    }
    __syncthreads();
#pragma unroll
    for (int i = 0; i < 4; i++) {
        int n = n0 + ty + i * 8;
        H[(size_t)n * DIM + k0 + tx] = __float2half_rn(tile[tx][ty + i * 8]);
    }
}

// ---------------------------------------------------------------------------
// Fused middle stage, warp-per-token, MMA-based (unchanged from R12 winner):
// RMSNorm+RoPE (lane-per-head, fp32 regs) -> S=QK^T via mma (m16n16k64) ->
// softmax on fragments (4-lane shfl) -> O=PV via mma (trans-ldmatrix V) ->
// fp16 out to ah. 8 warps/block = 8 tokens; no block-wide barriers.
// ---------------------------------------------------------------------------
__global__ __launch_bounds__(256)
void attn_kernel(const float* __restrict__ qkv,
                 const float* __restrict__ fcos, const float* __restrict__ fsin,
                 const float* __restrict__ g_q, const float* __restrict__ g_k,
                 __half* __restrict__ ah) {
    __shared__ __align__(16) __half sQ[8][NHEAD * HDIM];   // 2KB per warp
    __shared__ __align__(16) __half sK[8][NHEAD * HDIM];
    __shared__ __align__(16) __half sV[8][NHEAD * HDIM];

    const int w = threadIdx.x >> 5;
    const int lane = threadIdx.x & 31;
    const int token = blockIdx.x * 8 + w;
    const int n_idx = token & (SEQ - 1);
    const float* base = qkv + (size_t)token * QKVDIM;

    const uint32_t qb = s2u(&sQ[w][0]);
    const uint32_t kb = s2u(&sK[w][0]);
    const uint32_t vb = s2u(&sV[w][0]);

    // ---- Phase 1a: q (lanes 0-15) / k (lanes 16-31): one head per lane ----
    {
        const int hh = lane & 15;
        const float* src = base + (lane < 16 ? 0 : DIM) + hh * HDIM;
        float vr[64];
#pragma unroll
        for (int i = 0; i < 16; i++) ((float4*)vr)[i] = ((const float4*)src)[i];
        float ssum = 0.f;
#pragma unroll
        for (int e = 0; e < 64; e++) ssum += vr[e] * vr[e];
        float inv = 1.f / (sqrtf(ssum) * 0.125f + 1e-6f);   // ||x||*d^-0.5, d=64
        const float* gg = (lane < 16) ? g_q : g_k;

        union { __half2 h[4]; uint4 u; } pk[8];
#pragma unroll
        for (int p = 0; p < 32; p++) {
            float cc = fcos[n_idx * 32 + p];
            float sn = fsin[n_idx * 32 + p];
            float re = vr[2 * p] * inv * gg[2 * p];
            float im = vr[2 * p + 1] * inv * gg[2 * p + 1];
            pk[p >> 2].h[p & 3] = __floats2half2_rn(re * cc - im * sn,
                                                    re * sn + im * cc);
        }
        char* dst = (char*)((lane < 16) ? &sQ[w][0] : &sK[w][0]);
#pragma unroll
        for (int u = 0; u < 8; u++)
            *(uint4*)(dst + sw_off(hh, u)) = pk[u].u;
    }
    // ---- Phase 1b: v -> fp16 swizzled smem (each lane: half a row) ----
    {
        const float* vsrc = base + 2 * DIM + lane * 32;
        float4 vv[8];
#pragma unroll
        for (int i = 0; i < 8; i++) vv[i] = ((const float4*)vsrc)[i];
        const int row = lane >> 1, ub = (lane & 1) * 4;
        char* dst = (char*)&sV[w][0];
#pragma unroll
        for (int u2 = 0; u2 < 4; u2++) {
            union { __half2 h[4]; uint4 u; } pk;
            pk.h[0] = __floats2half2_rn(vv[2*u2].x, vv[2*u2].y);
            pk.h[1] = __floats2half2_rn(vv[2*u2].z, vv[2*u2].w);
            pk.h[2] = __floats2half2_rn(vv[2*u2+1].x, vv[2*u2+1].y);
            pk.h[3] = __floats2half2_rn(vv[2*u2+1].z, vv[2*u2+1].w);
            *(uint4*)(dst + sw_off(row, ub + u2)) = pk.u;
        }
    }
    __syncwarp();

    // ---- Phase 2: S = Q K^T (m16n16k64 => 2 n-tiles x 4 k16) ----
    float accS[2][4] = {{0.f,0.f,0.f,0.f},{0.f,0.f,0.f,0.f}};
#pragma unroll
    for (int kk = 0; kk < 4; kk++) {
        uint32_t a[4];
        {
            const int row = lane & 15;
            const int au = kk * 2 + (lane >> 4);
            ldsm_x4(a[0], a[1], a[2], a[3], qb + sw_off(row, au));
        }
        uint32_t b[4];
        {
            const int row = ((lane >> 4) & 1) * 8 + (lane & 7);
            const int bu = kk * 2 + ((lane >> 3) & 1);
            ldsm_x4(b[0], b[1], b[2], b[3], kb + sw_off(row, bu));
        }
        mma16816(accS[0], a, b);
        mma16816(accS[1], a, b + 2);
    }

    // ---- Phase 3: softmax over 16 cols (rows r=lane/4 and r+8) ----
    float m0 = fmaxf(fmaxf(accS[0][0], accS[0][1]), fmaxf(accS[1][0], accS[1][1]));
    float m1 = fmaxf(fmaxf(accS[0][2], accS[0][3]), fmaxf(accS[1][2], accS[1][3]));
    m0 = fmaxf(m0, __shfl_xor_sync(0xffffffffu, m0, 1));
    m0 = fmaxf(m0, __shfl_xor_sync(0xffffffffu, m0, 2));
    m1 = fmaxf(m1, __shfl_xor_sync(0xffffffffu, m1, 1));
    m1 = fmaxf(m1, __shfl_xor_sync(0xffffffffu, m1, 2));
    float e00 = __expf(0.125f * (accS[0][0] - m0));
    float e01 = __expf(0.125f * (accS[0][1] - m0));
    float e10 = __expf(0.125f * (accS[1][0] - m0));
    float e11 = __expf(0.125f * (accS[1][1] - m0));
    float f00 = __expf(0.125f * (accS[0][2] - m1));
    float f01 = __expf(0.125f * (accS[0][3] - m1));
    float f10 = __expf(0.125f * (accS[1][2] - m1));
    float f11 = __expf(0.125f * (accS[1][3] - m1));
    float s0 = e00 + e01 + e10 + e11;
    float s1 = f00 + f01 + f10 + f11;
    s0 += __shfl_xor_sync(0xffffffffu, s0, 1);
    s0 += __shfl_xor_sync(0xffffffffu, s0, 2);
    s1 += __shfl_xor_sync(0xffffffffu, s1, 1);
    s1 += __shfl_xor_sync(0xffffffffu, s1, 2);
    float r0i = 1.f / s0, r1i = 1.f / s1;

    // ---- Phase 4: P fragments ----
    uint32_t aP[4];
    {
        __half2 h;
        h = __floats2half2_rn(e00 * r0i, e01 * r0i); aP[0] = *(uint32_t*)&h;
        h = __floats2half2_rn(f00 * r1i, f01 * r1i); aP[1] = *(uint32_t*)&h;
        h = __floats2half2_rn(e10 * r0i, e11 * r0i); aP[2] = *(uint32_t*)&h;
        h = __floats2half2_rn(f10 * r1i, f11 * r1i); aP[3] = *(uint32_t*)&h;
    }

    // ---- Phase 5: O = P @ V (m16n64k16 => 8 n-tiles, trans-ldmatrix V) ----
    float accO[8][4];
#pragma unroll
    for (int t = 0; t < 8; t++)
#pragma unroll
        for (int e = 0; e < 4; e++) accO[t][e] = 0.f;
#pragma unroll
    for (int dt2 = 0; dt2 < 4; dt2++) {
        uint32_t b[4];
        const int grp = lane >> 3;
        const int krow = (grp & 1) * 8 + (lane & 7);
        const int dt = dt2 * 2 + (grp >> 1);
        ldsm_x4_t(b[0], b[1], b[2], b[3], vb + sw_off(krow, dt));
        mma16816(accO[2 * dt2], aP, b);
        mma16816(accO[2 * dt2 + 1], aP, b + 2);
    }

    // ---- Phase 6: write O to ah (fp16, row = head, col = d) ----
    {
        __half* orow = ah + (size_t)token * DIM;
        const int rr = lane >> 2, cc0 = 2 * (lane & 3);
#pragma unroll
        for (int t = 0; t < 8; t++) {
            *(__half2*)(orow + rr * HDIM + t * 8 + cc0) =
                __floats2half2_rn(accO[t][0], accO[t][1]);
            *(__half2*)(orow + (rr + 8) * HDIM + t * 8 + cc0) =
                __floats2half2_rn(accO[t][2], accO[t][3]);
        }
    }
}

// ---------------------------------------------------------------------------
extern "C" void kernel_launch(void* const* d_in, const int* in_sizes, int n_in,
                              void* d_out, int out_size) {
    const float* x     = (const float*)d_in[0];
    const float* fcos  = (const float*)d_in[1];
    const float* fsin  = (const float*)d_in[2];
    const float* wqkv  = (const float*)d_in[3];
    const float* gq    = (const float*)d_in[4];
    const float* gk    = (const float*)d_in[5];
    const float* wproj = (const float*)d_in[6];
    const float* bproj = (const float*)d_in[7];
    float* out = (float*)d_out;

    void *p_xh, *p_wqh, *p_wph, *p_ah, *p_qkv;
    cudaGetSymbolAddress(&p_xh,  g_xh);
    cudaGetSymbolAddress(&p_wqh, g_wqh);
    cudaGetSymbolAddress(&p_wph, g_wph);
    cudaGetSymbolAddress(&p_ah,  g_ah);
    cudaGetSymbolAddress(&p_qkv, g_qkv);

    cudaFuncSetAttribute((const void*)&mma_gemm<false, false>,
                         cudaFuncAttributeMaxDynamicSharedMemorySize, GEMM_SMEM);
    cudaFuncSetAttribute((const void*)&mma_gemm<true, false>,
                         cudaFuncAttributeMaxDynamicSharedMemorySize, GEMM_SMEM);

    {
        size_t total8 = (size_t)TOKENS * DIM / 8;
        convert_A_kernel<<<(unsigned)((total8 + 255) / 256), 256>>>(
            x, (__half*)p_xh, total8);
    }
    convert_W_kernel<<<dim3(QKVDIM / 32, DIM / 32), 256>>>(
        wqkv, (__half*)p_wqh, QKVDIM);
    convert_W_kernel<<<dim3(DIM / 32, DIM / 32), 256>>>(
        wproj, (__half*)p_wph, DIM);

    // qkv = x @ w_qkv  (single-pass fp16 MMA, fp32 accum, fp32 output)
    mma_gemm<false, false><<<dim3(QKVDIM / BN, TOKENS / BM), 128, GEMM_SMEM>>>(
        (const __half*)p_xh, (const __half*)p_wqh, nullptr, p_qkv, QKVDIM);

    // fused RMSNorm+RoPE+head-mixing attention (MMA) -> ah fp16
    attn_kernel<<<TOKENS / 8, 256>>>((const float*)p_qkv, fcos, fsin, gq, gk,
                                     (__half*)p_ah);

    // out = att @ w_proj + b  (fp32 output)
    mma_gemm<true, false><<<dim3(DIM / BN, TOKENS / BM), 128, GEMM_SMEM>>>(
        (const __half*)p_ah, (const __half*)p_wph, bproj, out, DIM);
}

// round 14
// speedup vs baseline: 8.4137x; 1.0671x over previous
#include <cuda_runtime.h>
#include <cuda_bf16.h>
#include <cuda_fp16.h>
#include <stdint.h>
#include <math.h>

// Problem constants: b=4, n=4096 -> T=16384 tokens, dim=1024, heads=16, d=64
#define TOKENS 16384
#define DIM    1024
#define QKVDIM 3072
#define NHEAD  16
#define HDIM   64
#define SEQ    4096

// GEMM tiling (K is always 1024)
#define BM 128
#define BN 128
#define BK 64
#define KCHUNKS (DIM / BK)          // 16
#define STAGES 3
#define ARR_BYTES (BM * BK * 2)     // 16384 per operand array per stage
#define STAGE_BYTES (2 * ARR_BYTES) // 32768 (A, B)
#define GEMM_SMEM (STAGES * STAGE_BYTES)  // 98304

// ---------------------------------------------------------------------------
// Scratch (device globals; kernel_launch is allocation-free)
// ---------------------------------------------------------------------------
__device__ __align__(256) __half g_xh  [(size_t)TOKENS * DIM];
__device__ __align__(256) __half g_wqh [(size_t)QKVDIM * DIM]; // [N,K]
__device__ __align__(256) __half g_wph [(size_t)DIM * DIM];    // [N,K]
__device__ __align__(256) __half g_ah  [(size_t)TOKENS * DIM];
__device__ __align__(256) __half g_qkv [(size_t)TOKENS * QKVDIM];  // fp16

// ---------------------------------------------------------------------------
// PTX helpers (baseline sm_80+ features only — tcgen05 unavailable on target)
// ---------------------------------------------------------------------------
__device__ __forceinline__ uint32_t s2u(const void* p) {
    uint32_t a;
    asm("{ .reg .u64 t; cvta.to.shared.u64 t, %1; cvt.u32.u64 %0, t; }"
        : "=r"(a) : "l"(p));
    return a;
}

__device__ __forceinline__ void cp_async16(uint32_t dst, const void* gsrc) {
    asm volatile("cp.async.cg.shared.global [%0], [%1], 16;"
                 :: "r"(dst), "l"(__cvta_generic_to_global(gsrc)) : "memory");
}
__device__ __forceinline__ void cp_commit() {
    asm volatile("cp.async.commit_group;" ::: "memory");
}
__device__ __forceinline__ void cp_wait1() {
    asm volatile("cp.async.wait_group 1;" ::: "memory");
}

__device__ __forceinline__ void ldsm_x4(uint32_t& r0, uint32_t& r1,
                                        uint32_t& r2, uint32_t& r3, uint32_t addr) {
    asm volatile("ldmatrix.sync.aligned.m8n8.x4.shared.b16 {%0,%1,%2,%3}, [%4];"
                 : "=r"(r0), "=r"(r1), "=r"(r2), "=r"(r3) : "r"(addr));
}
__device__ __forceinline__ void ldsm_x4_t(uint32_t& r0, uint32_t& r1,
                                          uint32_t& r2, uint32_t& r3, uint32_t addr) {
    asm volatile("ldmatrix.sync.aligned.m8n8.x4.trans.shared.b16 {%0,%1,%2,%3}, [%4];"
                 : "=r"(r0), "=r"(r1), "=r"(r2), "=r"(r3) : "r"(addr));
}

__device__ __forceinline__ void mma16816(float* c, const uint32_t* a, const uint32_t* b) {
    asm volatile(
        "mma.sync.aligned.m16n8k16.row.col.f32.f16.f16.f32 "
        "{%0,%1,%2,%3}, {%4,%5,%6,%7}, {%8,%9}, {%0,%1,%2,%3};"
        : "+f"(c[0]), "+f"(c[1]), "+f"(c[2]), "+f"(c[3])
        : "r"(a[0]), "r"(a[1]), "r"(a[2]), "r"(a[3]), "r"(b[0]), "r"(b[1]));
}

// Swizzled smem byte offset for a (row, 16B-unit) within a [rows][64] f16 tile.
__device__ __forceinline__ uint32_t sw_off(int row, int u) {
    return (uint32_t)(row * 128 + (((u ^ (row & 7)) & 7) << 4));
}

// ---------------------------------------------------------------------------
// GEMM: C[M,N] = A @ B^T, fp16 operands, fp32 accumulate.
// OUTHALF selects fp16 or fp32(+bias) output.
// grid (N/128, M/128), 128 threads = 4 warps, each warp 64x64.
// 2 CTAs/SM, 3-stage pipeline, prefetch distance 2 (cp.async.wait_group 1).
// ---------------------------------------------------------------------------
template <bool BIAS, bool OUTHALF>
__global__ __launch_bounds__(128, 2)
void mma_gemm(const __half* __restrict__ A, const __half* __restrict__ B,
              const float* __restrict__ bias, void* __restrict__ Cout, int N) {
    extern __shared__ __align__(256) char smem[];
    const uint32_t sb = s2u(smem);
    const int tid = threadIdx.x;
    const int wid = tid >> 5, lane = tid & 31;
    const int m0 = blockIdx.y * BM;
    const int n0 = blockIdx.x * BN;

    const __half* bases[2] = { A + (size_t)m0 * DIM, B + (size_t)n0 * DIM };

    // --- async stage loader: 2048 x 16B units per stage, 16 per thread ---
    auto load_stage = [&](int s, int c) {
#pragma unroll
        for (int i = 0; i < 16; i++) {
            int u = tid + i * 128;
            int arr = u >> 10;           // 0..1
            int idx = u & 1023;
            int row = idx >> 3;          // 0..127
            int cu  = idx & 7;           // 16B unit within 128B row
            const char* src = (const char*)bases[arr]
                              + (size_t)row * (DIM * 2) + c * (BK * 2) + cu * 16;
            uint32_t dst = sb + s * STAGE_BYTES + arr * ARR_BYTES + sw_off(row, cu);
            cp_async16(dst, src);
        }
    };

    load_stage(0, 0); cp_commit();
    load_stage(1, 1); cp_commit();

    const int wr = wid >> 1, wc = wid & 1;   // 2x2 warp grid
    const int wo = wr * 64, no = wc * 64;

    float acc[4][8][4];
#pragma unroll
    for (int mi = 0; mi < 4; mi++)
#pragma unroll
        for (int ni = 0; ni < 8; ni++)
#pragma unroll
            for (int e = 0; e < 4; e++) acc[mi][ni][e] = 0.f;

    const int la = lane & 15;

    for (int c = 0; c < KCHUNKS; c++) {
        cp_wait1();
        __syncthreads();
        const int cn = c + 2;
        if (cn < KCHUNKS) { load_stage(cn % STAGES, cn); cp_commit(); }
        else              { cp_commit(); }   // keep group count in step

        const uint32_t st = sb + (c % STAGES) * STAGE_BYTES;
        const uint32_t sA = st;
        const uint32_t sB = st + ARR_BYTES;

#pragma unroll
        for (int k16 = 0; k16 < 4; k16++) {
            // B fragments for all 8 ni via x4 ldmatrix pairs.
            uint32_t bh[8][2];
            const int brow_lo = (lane >> 4) & 1;         // which ni within pair
            const int bu = k16 * 2 + ((lane >> 3) & 1);  // k-unit
#pragma unroll
            for (int p = 0; p < 4; p++) {
                const int row = no + (p * 2 + brow_lo) * 8 + (lane & 7);
                uint32_t off = sw_off(row, bu);
                ldsm_x4(bh[p*2][0], bh[p*2][1], bh[p*2+1][0], bh[p*2+1][1], sB + off);
            }
            const int au = k16 * 2 + (lane >> 4);
#pragma unroll
            for (int mi = 0; mi < 4; mi++) {
                uint32_t ah[4];
                const int row = wo + mi * 16 + la;
                uint32_t off = sw_off(row, au);
                ldsm_x4(ah[0], ah[1], ah[2], ah[3], sA + off);
#pragma unroll
                for (int ni = 0; ni < 8; ni++) mma16816(acc[mi][ni], ah, bh[ni]);
            }
        }
    }

    // epilogue
    const int tg = lane >> 2, tq = lane & 3;
#pragma unroll
    for (int mi = 0; mi < 4; mi++) {
#pragma unroll
        for (int ni = 0; ni < 8; ni++) {
            const float* cc = acc[mi][ni];
            int col = n0 + no + ni * 8 + tq * 2;
            size_t r0 = (size_t)(m0 + wo + mi * 16 + tg);
            if (OUTHALF) {
                __half* C = (__half*)Cout;
                *(__half2*)(C + r0 * N + col) = __floats2half2_rn(cc[0], cc[1]);
                *(__half2*)(C + (r0 + 8) * N + col) = __floats2half2_rn(cc[2], cc[3]);
            } else {
                float* C = (float*)Cout;
                float bx = 0.f, by = 0.f;
                if (BIAS) { bx = bias[col]; by = bias[col + 1]; }
                float2 v0 = {cc[0] + bx, cc[1] + by};
                float2 v1 = {cc[2] + bx, cc[3] + by};
                *(float2*)(C + r0 * N + col) = v0;
                *(float2*)(C + (r0 + 8) * N + col) = v1;
            }
        }
    }
}

// ---------------------------------------------------------------------------
// Conversions
// ---------------------------------------------------------------------------
__global__ void convert_A_kernel(const float* __restrict__ X,
                                 __half* __restrict__ H, size_t total8) {
    size_t t = (size_t)blockIdx.x * blockDim.x + threadIdx.x;
    if (t >= total8) return;
    const float* src = X + t * 8;
    float4 f0 = *(const float4*)src;
    float4 f1 = *(const float4*)(src + 4);
    float v[8] = {f0.x, f0.y, f0.z, f0.w, f1.x, f1.y, f1.z, f1.w};
    union { __half b[8]; uint4 q; } Hh;
#pragma unroll
    for (int i = 0; i < 8; i++) Hh.b[i] = __float2half_rn(v[i]);
    ((uint4*)H)[t] = Hh.q;
}

__global__ void convert_W_kernel(const float* __restrict__ W,
                                 __half* __restrict__ H, int Nout) {
    __shared__ float tile[32][33];
    const int tx = threadIdx.x & 31, ty = threadIdx.x >> 5;
    const int n0 = blockIdx.x * 32, k0 = blockIdx.y * 32;
#pragma unroll
    for (int i = 0; i < 4; i++) {
        int k = k0 + ty + i * 8;
        tile[ty + i * 8][tx] = W[(size_t)k * Nout + n0 + tx];
    }
    __syncthreads();
#pragma unroll
    for (int i = 0; i < 4; i++) {
        int n = n0 + ty + i * 8;
        H[(size_t)n * DIM + k0 + tx] = __float2half_rn(tile[tx][ty + i * 8]);
    }
}

// ---------------------------------------------------------------------------
// Fused middle stage, warp-per-token, MMA-based; qkv input is fp16.
// RMSNorm+RoPE (lane-per-head, fp32 math in regs) -> S=QK^T via mma ->
// softmax on fragments (4-lane shfl) -> O=PV via mma (trans-ldmatrix V) ->
// fp16 out to ah. 8 warps/block = 8 tokens; no block-wide barriers.
// ---------------------------------------------------------------------------
__global__ __launch_bounds__(256)
void attn_kernel(const __half* __restrict__ qkv,
                 const float* __restrict__ fcos, const float* __restrict__ fsin,
                 const float* __restrict__ g_q, const float* __restrict__ g_k,
                 __half* __restrict__ ah) {
    __shared__ __align__(16) __half sQ[8][NHEAD * HDIM];   // 2KB per warp
    __shared__ __align__(16) __half sK[8][NHEAD * HDIM];
    __shared__ __align__(16) __half sV[8][NHEAD * HDIM];

    const int w = threadIdx.x >> 5;
    const int lane = threadIdx.x & 31;
    const int token = blockIdx.x * 8 + w;
    const int n_idx = token & (SEQ - 1);
    const __half* base = qkv + (size_t)token * QKVDIM;

    const uint32_t qb = s2u(&sQ[w][0]);
    const uint32_t kb = s2u(&sK[w][0]);
    const uint32_t vb = s2u(&sV[w][0]);

    // ---- Phase 1a: q (lanes 0-15) / k (lanes 16-31): one head per lane ----
    {
        const int hh = lane & 15;
        const __half* src = base + (lane < 16 ? 0 : DIM) + hh * HDIM;
        uint4 raw[8];
#pragma unroll
        for (int i = 0; i < 8; i++) raw[i] = ((const uint4*)src)[i];
        float vr[64];
#pragma unroll
        for (int i = 0; i < 8; i++) {
            const __half2* h2 = (const __half2*)&raw[i];
#pragma unroll
            for (int j = 0; j < 4; j++) {
                float2 f = __half22float2(h2[j]);
                vr[i * 8 + j * 2]     = f.x;
                vr[i * 8 + j * 2 + 1] = f.y;
            }
        }
        float ssum = 0.f;
#pragma unroll
        for (int e = 0; e < 64; e++) ssum += vr[e] * vr[e];
        float inv = 1.f / (sqrtf(ssum) * 0.125f + 1e-6f);   // ||x||*d^-0.5, d=64
        const float* gg = (lane < 16) ? g_q : g_k;

        union { __half2 h[4]; uint4 u; } pk[8];
#pragma unroll
        for (int p = 0; p < 32; p++) {
            float cc = fcos[n_idx * 32 + p];
            float sn = fsin[n_idx * 32 + p];
            float re = vr[2 * p] * inv * gg[2 * p];
            float im = vr[2 * p + 1] * inv * gg[2 * p + 1];
            pk[p >> 2].h[p & 3] = __floats2half2_rn(re * cc - im * sn,
                                                    re * sn + im * cc);
        }
        char* dst = (char*)((lane < 16) ? &sQ[w][0] : &sK[w][0]);
#pragma unroll
        for (int u = 0; u < 8; u++)
            *(uint4*)(dst + sw_off(hh, u)) = pk[u].u;
    }
    // ---- Phase 1b: v -> swizzled smem (fp16 passthrough, no conversion) ----
    {
        const int row = lane >> 1, ub = (lane & 1) * 4;
        const __half* vsrc = base + 2 * DIM + row * HDIM + (lane & 1) * 32;
        char* dst = (char*)&sV[w][0];
#pragma unroll
        for (int u2 = 0; u2 < 4; u2++) {
            uint4 d = ((const uint4*)vsrc)[u2];
            *(uint4*)(dst + sw_off(row, ub + u2)) = d;
        }
    }
    __syncwarp();

    // ---- Phase 2: S = Q K^T (m16n16k64 => 2 n-tiles x 4 k16) ----
    float accS[2][4] = {{0.f,0.f,0.f,0.f},{0.f,0.f,0.f,0.f}};
#pragma unroll
    for (int kk = 0; kk < 4; kk++) {
        uint32_t a[4];
        {
            const int row = lane & 15;
            const int au = kk * 2 + (lane >> 4);
            ldsm_x4(a[0], a[1], a[2], a[3], qb + sw_off(row, au));
        }
        uint32_t b[4];
        {
            const int row = ((lane >> 4) & 1) * 8 + (lane & 7);
            const int bu = kk * 2 + ((lane >> 3) & 1);
            ldsm_x4(b[0], b[1], b[2], b[3], kb + sw_off(row, bu));
        }
        mma16816(accS[0], a, b);
        mma16816(accS[1], a, b + 2);
    }

    // ---- Phase 3: softmax over 16 cols (rows r=lane/4 and r+8) ----
    float m0 = fmaxf(fmaxf(accS[0][0], accS[0][1]), fmaxf(accS[1][0], accS[1][1]));
    float m1 = fmaxf(fmaxf(accS[0][2], accS[0][3]), fmaxf(accS[1][2], accS[1][3]));
    m0 = fmaxf(m0, __shfl_xor_sync(0xffffffffu, m0, 1));
    m0 = fmaxf(m0, __shfl_xor_sync(0xffffffffu, m0, 2));
    m1 = fmaxf(m1, __shfl_xor_sync(0xffffffffu, m1, 1));
    m1 = fmaxf(m1, __shfl_xor_sync(0xffffffffu, m1, 2));
    float e00 = __expf(0.125f * (accS[0][0] - m0));
    float e01 = __expf(0.125f * (accS[0][1] - m0));
    float e10 = __expf(0.125f * (accS[1][0] - m0));
    float e11 = __expf(0.125f * (accS[1][1] - m0));
    float f00 = __expf(0.125f * (accS[0][2] - m1));
    float f01 = __expf(0.125f * (accS[0][3] - m1));
    float f10 = __expf(0.125f * (accS[1][2] - m1));
    float f11 = __expf(0.125f * (accS[1][3] - m1));
    float s0 = e00 + e01 + e10 + e11;
    float s1 = f00 + f01 + f10 + f11;
    s0 += __shfl_xor_sync(0xffffffffu, s0, 1);
    s0 += __shfl_xor_sync(0xffffffffu, s0, 2);
    s1 += __shfl_xor_sync(0xffffffffu, s1, 1);
    s1 += __shfl_xor_sync(0xffffffffu, s1, 2);
    float r0i = 1.f / s0, r1i = 1.f / s1;

    // ---- Phase 4: P fragments ----
    uint32_t aP[4];
    {
        __half2 h;
        h = __floats2half2_rn(e00 * r0i, e01 * r0i); aP[0] = *(uint32_t*)&h;
        h = __floats2half2_rn(f00 * r1i, f01 * r1i); aP[1] = *(uint32_t*)&h;
        h = __floats2half2_rn(e10 * r0i, e11 * r0i); aP[2] = *(uint32_t*)&h;
        h = __floats2half2_rn(f10 * r1i, f11 * r1i); aP[3] = *(uint32_t*)&h;
    }

    // ---- Phase 5: O = P @ V (m16n64k16 => 8 n-tiles, trans-ldmatrix V) ----
    float accO[8][4];
#pragma unroll
    for (int t = 0; t < 8; t++)
#pragma unroll
        for (int e = 0; e < 4; e++) accO[t][e] = 0.f;
#pragma unroll
    for (int dt2 = 0; dt2 < 4; dt2++) {
        uint32_t b[4];
        const int grp = lane >> 3;
        const int krow = (grp & 1) * 8 + (lane & 7);
        const int dt = dt2 * 2 + (grp >> 1);
        ldsm_x4_t(b[0], b[1], b[2], b[3], vb + sw_off(krow, dt));
        mma16816(accO[2 * dt2], aP, b);
        mma16816(accO[2 * dt2 + 1], aP, b + 2);
    }

    // ---- Phase 6: write O to ah (fp16, row = head, col = d) ----
    {
        __half* orow = ah + (size_t)token * DIM;
        const int rr = lane >> 2, cc0 = 2 * (lane & 3);
#pragma unroll
        for (int t = 0; t < 8; t++) {
            *(__half2*)(orow + rr * HDIM + t * 8 + cc0) =
                __floats2half2_rn(accO[t][0], accO[t][1]);
            *(__half2*)(orow + (rr + 8) * HDIM + t * 8 + cc0) =
                __floats2half2_rn(accO[t][2], accO[t][3]);
        }
    }
}

// ---------------------------------------------------------------------------
extern "C" void kernel_launch(void* const* d_in, const int* in_sizes, int n_in,
                              void* d_out, int out_size) {
    const float* x     = (const float*)d_in[0];
    const float* fcos  = (const float*)d_in[1];
    const float* fsin  = (const float*)d_in[2];
    const float* wqkv  = (const float*)d_in[3];
    const float* gq    = (const float*)d_in[4];
    const float* gk    = (const float*)d_in[5];
    const float* wproj = (const float*)d_in[6];
    const float* bproj = (const float*)d_in[7];
    float* out = (float*)d_out;

    void *p_xh, *p_wqh, *p_wph, *p_ah, *p_qkv;
    cudaGetSymbolAddress(&p_xh,  g_xh);
    cudaGetSymbolAddress(&p_wqh, g_wqh);
    cudaGetSymbolAddress(&p_wph, g_wph);
    cudaGetSymbolAddress(&p_ah,  g_ah);
    cudaGetSymbolAddress(&p_qkv, g_qkv);

    cudaFuncSetAttribute((const void*)&mma_gemm<false, true>,
                         cudaFuncAttributeMaxDynamicSharedMemorySize, GEMM_SMEM);
    cudaFuncSetAttribute((const void*)&mma_gemm<true, false>,
                         cudaFuncAttributeMaxDynamicSharedMemorySize, GEMM_SMEM);

    {
        size_t total8 = (size_t)TOKENS * DIM / 8;
        convert_A_kernel<<<(unsigned)((total8 + 255) / 256), 256>>>(
            x, (__half*)p_xh, total8);
    }
    convert_W_kernel<<<dim3(QKVDIM / 32, DIM / 32), 256>>>(
        wqkv, (__half*)p_wqh, QKVDIM);
    convert_W_kernel<<<dim3(DIM / 32, DIM / 32), 256>>>(
        wproj, (__half*)p_wph, DIM);

    // qkv = x @ w_qkv  (single-pass fp16 MMA, fp32 accum, fp16 output)
    mma_gemm<false, true><<<dim3(QKVDIM / BN, TOKENS / BM), 128, GEMM_SMEM>>>(
        (const __half*)p_xh, (const __half*)p_wqh, nullptr, p_qkv, QKVDIM);

    // fused RMSNorm+RoPE+head-mixing attention (MMA) -> ah fp16
    attn_kernel<<<TOKENS / 8, 256>>>((const __half*)p_qkv, fcos, fsin, gq, gk,
                                     (__half*)p_ah);

    // out = att @ w_proj + b  (fp32 output)
    mma_gemm<true, false><<<dim3(DIM / BN, TOKENS / BM), 128, GEMM_SMEM>>>(
        (const __half*)p_ah, (const __half*)p_wph, bproj, out, DIM);
}